// round 4
// baseline (speedup 1.0000x reference)
#include <cuda_runtime.h>

#define BATCH 16
#define HEADS 12
#define DIM 64
#define FEAT 768
#define LSEQ 1025
#define MROWS (BATCH * LSEQ)   // 16400
#define EPSF 1e-8f

// Scratch (allocation-free rule: __device__ globals)
__device__ float g_q[(size_t)BATCH * HEADS * LSEQ * DIM];
__device__ float g_k[(size_t)BATCH * HEADS * LSEQ * DIM];
__device__ float g_v[(size_t)BATCH * HEADS * LSEQ * DIM];
__device__ float g_o[(size_t)MROWS * FEAT];

// ---------------------------------------------------------------------------
// GEMM: C = A[M,768] * W[768,768] + bias, with per-mode epilogue.
// MODE 0: q = relu((acc+b)/8) + eps   -> g_q laid out [B][H][L][D]
// MODE 1: k = relu(acc+b) + eps       -> g_k [B][H][L][D]
// MODE 2: v = acc+b                   -> g_v [B][H][L][D]
// MODE 3: out = acc+b                 -> d_out [M][768] row-major
// 64x64 tile, BK=16, 256 threads, 4x4 microtile, float4 smem paths.
// ---------------------------------------------------------------------------
template <int MODE>
__global__ __launch_bounds__(256) void gemm_kernel(
    const float* __restrict__ A, const float* __restrict__ W,
    const float* __restrict__ bias, float* __restrict__ C)
{
    __shared__ float As[16][68];   // As[k][m] (transposed)
    __shared__ float Ws[16][68];   // Ws[k][n]

    const int tid = threadIdx.x;
    const int tx = tid & 15, ty = tid >> 4;
    const int row0 = blockIdx.x * 64;
    const int col0 = blockIdx.y * 64;

    const int lm  = tid >> 2;        // 0..63 : m row for A load
    const int lk4 = (tid & 3) * 4;   // k sub-offset for A load
    const int wn4 = (tid & 15) * 4;  // n offset for W load
    const int wk  = tid >> 4;        // 0..15 : k row for W load

    float acc[4][4];
#pragma unroll
    for (int i = 0; i < 4; i++)
#pragma unroll
        for (int j = 0; j < 4; j++) acc[i][j] = 0.f;

    const int grow = row0 + lm;
    const float* aptr = A + (size_t)grow * FEAT + lk4;
    const float* wptr = W + (size_t)wk * FEAT + col0 + wn4;

    for (int k0 = 0; k0 < FEAT; k0 += 16) {
        float4 av = make_float4(0.f, 0.f, 0.f, 0.f);
        if (grow < MROWS) av = *(const float4*)(aptr + k0);
        As[lk4 + 0][lm] = av.x;
        As[lk4 + 1][lm] = av.y;
        As[lk4 + 2][lm] = av.z;
        As[lk4 + 3][lm] = av.w;
        *(float4*)&Ws[wk][wn4] = *(const float4*)(wptr + (size_t)k0 * FEAT);
        __syncthreads();
#pragma unroll
        for (int kk = 0; kk < 16; kk++) {
            float4 a4 = *(float4*)&As[kk][ty * 4];
            float4 b4 = *(float4*)&Ws[kk][tx * 4];
            float a[4] = {a4.x, a4.y, a4.z, a4.w};
            float bb[4] = {b4.x, b4.y, b4.z, b4.w};
#pragma unroll
            for (int i = 0; i < 4; i++)
#pragma unroll
                for (int j = 0; j < 4; j++)
                    acc[i][j] = fmaf(a[i], bb[j], acc[i][j]);
        }
        __syncthreads();
    }

#pragma unroll
    for (int i = 0; i < 4; i++) {
        int r = row0 + ty * 4 + i;
        if (r >= MROWS) continue;
#pragma unroll
        for (int j = 0; j < 4; j++) {
            int c = col0 + tx * 4 + j;
            float v = acc[i][j] + bias[c];
            if (MODE == 0) v = fmaxf(v * 0.125f, 0.f) + EPSF;  // /sqrt(64), relu, +eps
            if (MODE == 1) v = fmaxf(v, 0.f) + EPSF;
            if (MODE == 3) {
                C[(size_t)r * FEAT + c] = v;
            } else {
                int b = r / LSEQ, l = r - b * LSEQ;
                int h = c >> 6, d = c & 63;
                C[(((size_t)(b * HEADS + h)) * LSEQ + l) * DIM + d] = v;
            }
        }
    }
}

// ---------------------------------------------------------------------------
// Fused attention: per (b, h, 64-query tile).
// s = (q . k) * |tm| + eps  (tm from per-head 4096-entry Toeplitz table,
//  tm==1 on CLS row/col); running rowsum + out accumulation; divide at end.
// ---------------------------------------------------------------------------
__global__ __launch_bounds__(256) void attn_kernel(const float* __restrict__ tpar,
                                                   float* __restrict__ outp)
{
    extern __shared__ float sm[];
    float* tp = sm;                 // 4096 : toeplitz table for head h
    float* qs = sm + 4096;          // [64 d][68] : q transposed (d-major)
    float* ks = qs + 64 * 68;       // [64 d][68] : k transposed
    float* vs = ks + 64 * 68;       // [64 tk][68 d]
    float* st = vs + 64 * 68;       // [64 tk][68 q] : masked scores (transposed)

    const int tid = threadIdx.x;
    const int tx = tid & 15, ty = tid >> 4;
    const int q0 = blockIdx.x * 64;
    const int h = blockIdx.y;
    const int b = blockIdx.z;

    const float* qp = g_q + ((size_t)(b * HEADS + h)) * LSEQ * DIM;
    const float* kp = g_k + ((size_t)(b * HEADS + h)) * LSEQ * DIM;
    const float* vp = g_v + ((size_t)(b * HEADS + h)) * LSEQ * DIM;

    for (int i = tid; i < 4096; i += 256) tp[i] = tpar[h * 4096 + i];

    const int lt = tid >> 2;         // token 0..63
    const int ld4 = (tid & 3) * 4;   // d sub-offset within a 16-wide chunk
    {
        int qg = q0 + lt;
#pragma unroll
        for (int r = 0; r < 4; r++) {       // 4 chunks of 16 d-values -> full D=64
            int d0 = r * 16 + ld4;
            float4 v = make_float4(0.f, 0.f, 0.f, 0.f);
            if (qg < LSEQ) v = *(const float4*)&qp[(size_t)qg * DIM + d0];
            qs[(d0 + 0) * 68 + lt] = v.x;
            qs[(d0 + 1) * 68 + lt] = v.y;
            qs[(d0 + 2) * 68 + lt] = v.z;
            qs[(d0 + 3) * 68 + lt] = v.w;
        }
    }

    float outv[4][4];
#pragma unroll
    for (int i = 0; i < 4; i++)
#pragma unroll
        for (int j = 0; j < 4; j++) outv[i][j] = 0.f;
    float rs[4] = {0.f, 0.f, 0.f, 0.f};

    for (int kt = 0; kt < LSEQ; kt += 64) {
        __syncthreads();  // ks/vs reuse (also covers initial qs/tp writes)
        {
            int kg = kt + lt;
#pragma unroll
            for (int r = 0; r < 4; r++) {   // full D=64 for k and v
                int d0 = r * 16 + ld4;
                float4 kv = make_float4(0.f, 0.f, 0.f, 0.f);
                float4 vv = make_float4(0.f, 0.f, 0.f, 0.f);
                if (kg < LSEQ) {
                    kv = *(const float4*)&kp[(size_t)kg * DIM + d0];
                    vv = *(const float4*)&vp[(size_t)kg * DIM + d0];
                }
                ks[(d0 + 0) * 68 + lt] = kv.x;
                ks[(d0 + 1) * 68 + lt] = kv.y;
                ks[(d0 + 2) * 68 + lt] = kv.z;
                ks[(d0 + 3) * 68 + lt] = kv.w;
                *(float4*)&vs[lt * 68 + d0] = vv;
            }
        }
        __syncthreads();

        // Phase 1: s[4q][4k] = q . k over D=64
        float s[4][4];
#pragma unroll
        for (int i = 0; i < 4; i++)
#pragma unroll
            for (int j = 0; j < 4; j++) s[i][j] = 0.f;
#pragma unroll 16
        for (int d = 0; d < 64; d++) {
            float4 a4 = *(float4*)&qs[d * 68 + ty * 4];
            float4 b4 = *(float4*)&ks[d * 68 + tx * 4];
            float a[4] = {a4.x, a4.y, a4.z, a4.w};
            float bb[4] = {b4.x, b4.y, b4.z, b4.w};
#pragma unroll
            for (int i = 0; i < 4; i++)
#pragma unroll
                for (int j = 0; j < 4; j++)
                    s[i][j] = fmaf(a[i], bb[j], s[i][j]);
        }

        // mask + eps, rowsum partials, write transposed scores
#pragma unroll
        for (int i = 0; i < 4; i++) {
            int qg = q0 + ty * 4 + i;
            int qgi = (qg - 1) >> 5;
            int qgj = (qg - 1) & 31;
#pragma unroll
            for (int j = 0; j < 4; j++) {
                int kg = kt + tx * 4 + j;
                float val = 0.f;
                if (kg < LSEQ && qg < LSEQ) {
                    float tm = 1.f;
                    if (qg != 0 && kg != 0) {
                        int ki = kg - 1;
                        int di = qgi - (ki >> 5) + 32;
                        int dj = qgj - (ki & 31) + 32;
                        tm = fabsf(tp[di * 64 + dj]);
                    }
                    val = s[i][j] * tm + EPSF;
                }
                st[(tx * 4 + j) * 68 + ty * 4 + i] = val;
                rs[i] += val;
            }
        }
        __syncthreads();

        // Phase 2: out[4q][4d] += s[q][tk] * v[tk][d]
#pragma unroll 16
        for (int tk = 0; tk < 64; tk++) {
            float4 s4 = *(float4*)&st[tk * 68 + ty * 4];
            float4 v4 = *(float4*)&vs[tk * 68 + tx * 4];
            float sv[4] = {s4.x, s4.y, s4.z, s4.w};
            float vv[4] = {v4.x, v4.y, v4.z, v4.w};
#pragma unroll
            for (int i = 0; i < 4; i++)
#pragma unroll
                for (int j = 0; j < 4; j++)
                    outv[i][j] = fmaf(sv[i], vv[j], outv[i][j]);
        }
    }
    __syncthreads();

    // rowsum reduce across the 16 tx threads (reuse st as [64][17])
#pragma unroll
    for (int i = 0; i < 4; i++)
        st[(ty * 4 + i) * 17 + tx] = rs[i];
    __syncthreads();

#pragma unroll
    for (int i = 0; i < 4; i++) {
        int qg = q0 + ty * 4 + i;
        if (qg >= LSEQ) continue;
        float tot = 0.f;
#pragma unroll
        for (int t = 0; t < 16; t++) tot += st[(ty * 4 + i) * 17 + t];
        float inv = 1.f / tot;
        float4 o4 = make_float4(outv[i][0] * inv, outv[i][1] * inv,
                                outv[i][2] * inv, outv[i][3] * inv);
        *(float4*)&outp[((size_t)(b * LSEQ + qg)) * FEAT + h * DIM + tx * 4] = o4;
    }
}

// ---------------------------------------------------------------------------
extern "C" void kernel_launch(void* const* d_in, const int* in_sizes, int n_in,
                              void* d_out, int out_size)
{
    const float* x    = (const float*)d_in[0];
    const float* wq   = (const float*)d_in[1];
    const float* bq   = (const float*)d_in[2];
    const float* wk   = (const float*)d_in[3];
    const float* bk   = (const float*)d_in[4];
    const float* wv   = (const float*)d_in[5];
    const float* bv   = (const float*)d_in[6];
    const float* wo   = (const float*)d_in[7];
    const float* bo   = (const float*)d_in[8];
    const float* tpar = (const float*)d_in[9];
    float* out = (float*)d_out;

    float *qp, *kp, *vp, *op;
    cudaGetSymbolAddress((void**)&qp, g_q);
    cudaGetSymbolAddress((void**)&kp, g_k);
    cudaGetSymbolAddress((void**)&vp, g_v);
    cudaGetSymbolAddress((void**)&op, g_o);

    dim3 gg((MROWS + 63) / 64, FEAT / 64);
    gemm_kernel<0><<<gg, 256>>>(x, wq, bq, qp);
    gemm_kernel<1><<<gg, 256>>>(x, wk, bk, kp);
    gemm_kernel<2><<<gg, 256>>>(x, wv, bv, vp);

    const int smem_bytes = (4096 + 4 * 64 * 68) * 4;  // 86016
    cudaFuncSetAttribute(attn_kernel, cudaFuncAttributeMaxDynamicSharedMemorySize,
                         smem_bytes);
    attn_kernel<<<dim3(17, HEADS, BATCH), 256, smem_bytes>>>(tpar, op);

    gemm_kernel<3><<<gg, 256>>>(op, wo, bo, out);
}

// round 8
// speedup vs baseline: 1.1218x; 1.1218x over previous
#include <cuda_runtime.h>
#include <cuda_bf16.h>
#include <cstdint>

#define BATCH 16
#define HEADS 12
#define DIM 64
#define FEAT 768
#define LSEQ 1025
#define MROWS (BATCH * LSEQ)   // 16400
#define EPSF 1e-8f

// Scratch (allocation-free rule: __device__ globals)
__device__ float g_q[(size_t)BATCH * HEADS * LSEQ * DIM];
__device__ float g_k[(size_t)BATCH * HEADS * LSEQ * DIM];
__device__ float g_v[(size_t)BATCH * HEADS * LSEQ * DIM];
__device__ float g_o[(size_t)MROWS * FEAT];

// ---------------------------------------------------------------------------
// helpers
// ---------------------------------------------------------------------------
__device__ __forceinline__ uint32_t smem_u32(const void* p) {
    uint32_t a;
    asm("{ .reg .u64 t; cvta.to.shared.u64 t, %1; cvt.u32.u64 %0, t; }"
        : "=r"(a) : "l"(p));
    return a;
}
__device__ __forceinline__ void ldsm4(uint32_t* r, uint32_t addr) {
    asm volatile("ldmatrix.sync.aligned.m8n8.x4.shared.b16 {%0,%1,%2,%3}, [%4];"
                 : "=r"(r[0]), "=r"(r[1]), "=r"(r[2]), "=r"(r[3]) : "r"(addr));
}
__device__ __forceinline__ void mma16816(float* d, const uint32_t* a, const uint32_t* b) {
    asm volatile("mma.sync.aligned.m16n8k16.row.col.f32.bf16.bf16.f32 "
                 "{%0,%1,%2,%3}, {%4,%5,%6,%7}, {%8,%9}, {%0,%1,%2,%3};"
                 : "+f"(d[0]), "+f"(d[1]), "+f"(d[2]), "+f"(d[3])
                 : "r"(a[0]), "r"(a[1]), "r"(a[2]), "r"(a[3]),
                   "r"(b[0]), "r"(b[1]));
}
// split fp32 pair into packed bf16x2 hi and lo words
__device__ __forceinline__ void split2(float a, float b, uint32_t& hi, uint32_t& lo) {
    __nv_bfloat16 ha = __float2bfloat16(a), hb = __float2bfloat16(b);
    float ra = a - __bfloat162float(ha), rb = b - __bfloat162float(hb);
    __nv_bfloat162 h; h.x = ha; h.y = hb;
    __nv_bfloat162 l; l.x = __float2bfloat16(ra); l.y = __float2bfloat16(rb);
    hi = *(uint32_t*)&h;
    lo = *(uint32_t*)&l;
}

// ---------------------------------------------------------------------------
// Tensor-core GEMM via mma.sync (bf16 hi/lo 3-pass, fp32 accum)
// C = A[M,768] * W[768,768] + bias.
// CTA tile 128x128, BK=32, 8 warps (4x2), warp tile 32x64.
// smem: A[m][k] (hi,lo) rows 80B; BT[n][k] (hi,lo) rows 80B.
// MODE 0: q=relu((acc+b)/8)+eps -> g_q[B][H][L][D]
// MODE 1: k=relu(acc+b)+eps     -> g_k
// MODE 2: v=acc+b               -> g_v
// MODE 3: out=acc+b             -> C row-major [M,768]
// ---------------------------------------------------------------------------
#define ROWB 80    // smem row stride (bytes) for 32 bf16 + pad

template <int MODE>
__global__ __launch_bounds__(256, 1) void tgemm(
    const float* __restrict__ A, const float* __restrict__ W,
    const float* __restrict__ bias, float* __restrict__ C)
{
    __shared__ __align__(16) char smA[2][128 * ROWB];   // hi, lo
    __shared__ __align__(16) char smB[2][128 * ROWB];   // hi, lo (BT[n][k])

    const int tid = threadIdx.x;
    const int wid = tid >> 5, lane = tid & 31;
    const int m0 = blockIdx.x * 128, n0 = blockIdx.y * 128;

    const int mw = (wid >> 1) * 32;       // warp m offset
    const int nw = (wid & 1) * 64;        // warp n offset

    const uint32_t baseAh = smem_u32(smA[0]);
    const uint32_t baseAl = smem_u32(smA[1]);
    const uint32_t baseBh = smem_u32(smB[0]);
    const uint32_t baseBl = smem_u32(smB[1]);

    // A loader: row = tid>>1, 16-float half = (tid&1)*16
    const int ar = tid >> 1, ah16 = (tid & 1) * 16;
    const bool aval = (m0 + ar) < MROWS;
    const float* abase = A + (size_t)(m0 + ar) * FEAT + ah16;

    float acc[2][8][4];
#pragma unroll
    for (int i = 0; i < 2; i++)
#pragma unroll
        for (int j = 0; j < 8; j++)
#pragma unroll
            for (int q = 0; q < 4; q++) acc[i][j][q] = 0.f;

    for (int k0 = 0; k0 < FEAT; k0 += 32) {
        // ---- load + convert A tile [128][32] ----
        {
            const float4* src = (const float4*)(abase + k0);
#pragma unroll
            for (int i = 0; i < 4; i++) {
                float4 v = aval ? src[i] : make_float4(0.f, 0.f, 0.f, 0.f);
                uint32_t h0, l0, h1, l1;
                split2(v.x, v.y, h0, l0);
                split2(v.z, v.w, h1, l1);
                const int off = ar * ROWB + (ah16 + i * 4) * 2;
                *(uint32_t*)(smA[0] + off)     = h0;
                *(uint32_t*)(smA[0] + off + 4) = h1;
                *(uint32_t*)(smA[1] + off)     = l0;
                *(uint32_t*)(smA[1] + off + 4) = l1;
            }
        }
        // ---- load + transpose + convert W tile [32][128] -> BT[n][k] ----
        {
#pragma unroll
            for (int t = 0; t < 2; t++) {
                const int id = t * 256 + tid;       // 512 items: 16 kpairs x 32 n4
                const int kp = id >> 5;             // 0..15
                const int n4 = (id & 31) << 2;      // 0..124
                const float* w0 = W + (size_t)(k0 + 2 * kp) * FEAT + n0 + n4;
                float4 r0 = *(const float4*)w0;
                float4 r1 = *(const float4*)(w0 + FEAT);
                const float e0[4] = {r0.x, r0.y, r0.z, r0.w};
                const float e1[4] = {r1.x, r1.y, r1.z, r1.w};
#pragma unroll
                for (int j = 0; j < 4; j++) {
                    uint32_t h, l;
                    split2(e0[j], e1[j], h, l);     // (k even, k odd) for col n4+j
                    const int off = (n4 + j) * ROWB + kp * 4;
                    *(uint32_t*)(smB[0] + off) = h;
                    *(uint32_t*)(smB[1] + off) = l;
                }
            }
        }
        __syncthreads();

        // ---- mma: 2 k16 steps x 3 passes ----
#pragma unroll
        for (int ks = 0; ks < 2; ks++) {
            const int kloc = ks * 16;
            uint32_t ah[2][4], al[2][4], bb[4][4];
            // A frags (hi & lo)
#pragma unroll
            for (int mf = 0; mf < 2; mf++) {
                const uint32_t off =
                    (uint32_t)(mw + mf * 16 + (lane & 15)) * ROWB
                    + (uint32_t)(kloc + (lane >> 4) * 8) * 2;
                ldsm4(ah[mf], baseAh + off);
                ldsm4(al[mf], baseAl + off);
            }
            // B offsets (per 16-n chunk)
            uint32_t boff[4];
#pragma unroll
            for (int c = 0; c < 4; c++)
                boff[c] = (uint32_t)(nw + c * 16 + (lane & 7) + ((lane >> 4) & 1) * 8) * ROWB
                        + (uint32_t)(kloc + ((lane >> 3) & 1) * 8) * 2;

            // pass hh + lh with B-hi
#pragma unroll
            for (int c = 0; c < 4; c++) ldsm4(bb[c], baseBh + boff[c]);
#pragma unroll
            for (int mf = 0; mf < 2; mf++)
#pragma unroll
                for (int nf = 0; nf < 8; nf++) {
                    const uint32_t* bp = &bb[nf >> 1][(nf & 1) * 2];
                    mma16816(acc[mf][nf], ah[mf], bp);
                    mma16816(acc[mf][nf], al[mf], bp);
                }
            // pass hl with B-lo
#pragma unroll
            for (int c = 0; c < 4; c++) ldsm4(bb[c], baseBl + boff[c]);
#pragma unroll
            for (int mf = 0; mf < 2; mf++)
#pragma unroll
                for (int nf = 0; nf < 8; nf++)
                    mma16816(acc[mf][nf], ah[mf], &bb[nf >> 1][(nf & 1) * 2]);
        }
        __syncthreads();
    }

    // ---- epilogue ----
#pragma unroll
    for (int mf = 0; mf < 2; mf++) {
#pragma unroll
        for (int half = 0; half < 2; half++) {
            const int r = m0 + mw + mf * 16 + (lane >> 2) + half * 8;
            if (r >= MROWS) continue;
            int bb2 = 0, l = 0;
            if (MODE != 3) { bb2 = r / LSEQ; l = r - bb2 * LSEQ; }
#pragma unroll
            for (int nf = 0; nf < 8; nf++) {
                const int c = n0 + nw + nf * 8 + (lane & 3) * 2;
                float v0 = acc[mf][nf][half * 2 + 0] + bias[c];
                float v1 = acc[mf][nf][half * 2 + 1] + bias[c + 1];
                if (MODE == 0) {
                    v0 = fmaxf(v0 * 0.125f, 0.f) + EPSF;
                    v1 = fmaxf(v1 * 0.125f, 0.f) + EPSF;
                } else if (MODE == 1) {
                    v0 = fmaxf(v0, 0.f) + EPSF;
                    v1 = fmaxf(v1, 0.f) + EPSF;
                }
                float2 o = make_float2(v0, v1);
                if (MODE == 3) {
                    *(float2*)&C[(size_t)r * FEAT + c] = o;
                } else {
                    const int h = c >> 6, d = c & 63;
                    *(float2*)&C[(((size_t)(bb2 * HEADS + h)) * LSEQ + l) * DIM + d] = o;
                }
            }
        }
    }
}

// ---------------------------------------------------------------------------
// Fused attention (fp32, unchanged from passing R4 version)
// ---------------------------------------------------------------------------
__global__ __launch_bounds__(256) void attn_kernel(const float* __restrict__ tpar,
                                                   float* __restrict__ outp)
{
    extern __shared__ float smf[];
    float* tp = smf;                 // 4096 : toeplitz table for head h
    float* qs = smf + 4096;          // [64 d][68] : q transposed (d-major)
    float* ks = qs + 64 * 68;        // [64 d][68] : k transposed
    float* vs = ks + 64 * 68;        // [64 tk][68 d]
    float* st = vs + 64 * 68;        // [64 tk][68 q] : masked scores (transposed)

    const int tid = threadIdx.x;
    const int tx = tid & 15, ty = tid >> 4;
    const int q0 = blockIdx.x * 64;
    const int h = blockIdx.y;
    const int b = blockIdx.z;

    const float* qp = g_q + ((size_t)(b * HEADS + h)) * LSEQ * DIM;
    const float* kp = g_k + ((size_t)(b * HEADS + h)) * LSEQ * DIM;
    const float* vp = g_v + ((size_t)(b * HEADS + h)) * LSEQ * DIM;

    for (int i = tid; i < 4096; i += 256) tp[i] = tpar[h * 4096 + i];

    const int lt = tid >> 2;
    const int ld4 = (tid & 3) * 4;
    {
        int qg = q0 + lt;
#pragma unroll
        for (int r = 0; r < 4; r++) {
            int d0 = r * 16 + ld4;
            float4 v = make_float4(0.f, 0.f, 0.f, 0.f);
            if (qg < LSEQ) v = *(const float4*)&qp[(size_t)qg * DIM + d0];
            qs[(d0 + 0) * 68 + lt] = v.x;
            qs[(d0 + 1) * 68 + lt] = v.y;
            qs[(d0 + 2) * 68 + lt] = v.z;
            qs[(d0 + 3) * 68 + lt] = v.w;
        }
    }

    float outv[4][4];
#pragma unroll
    for (int i = 0; i < 4; i++)
#pragma unroll
        for (int j = 0; j < 4; j++) outv[i][j] = 0.f;
    float rs[4] = {0.f, 0.f, 0.f, 0.f};

    for (int kt = 0; kt < LSEQ; kt += 64) {
        __syncthreads();
        {
            int kg = kt + lt;
#pragma unroll
            for (int r = 0; r < 4; r++) {
                int d0 = r * 16 + ld4;
                float4 kv = make_float4(0.f, 0.f, 0.f, 0.f);
                float4 vv = make_float4(0.f, 0.f, 0.f, 0.f);
                if (kg < LSEQ) {
                    kv = *(const float4*)&kp[(size_t)kg * DIM + d0];
                    vv = *(const float4*)&vp[(size_t)kg * DIM + d0];
                }
                ks[(d0 + 0) * 68 + lt] = kv.x;
                ks[(d0 + 1) * 68 + lt] = kv.y;
                ks[(d0 + 2) * 68 + lt] = kv.z;
                ks[(d0 + 3) * 68 + lt] = kv.w;
                *(float4*)&vs[lt * 68 + d0] = vv;
            }
        }
        __syncthreads();

        float s[4][4];
#pragma unroll
        for (int i = 0; i < 4; i++)
#pragma unroll
            for (int j = 0; j < 4; j++) s[i][j] = 0.f;
#pragma unroll 16
        for (int d = 0; d < 64; d++) {
            float4 a4 = *(float4*)&qs[d * 68 + ty * 4];
            float4 b4 = *(float4*)&ks[d * 68 + tx * 4];
            float a[4] = {a4.x, a4.y, a4.z, a4.w};
            float bbv[4] = {b4.x, b4.y, b4.z, b4.w};
#pragma unroll
            for (int i = 0; i < 4; i++)
#pragma unroll
                for (int j = 0; j < 4; j++)
                    s[i][j] = fmaf(a[i], bbv[j], s[i][j]);
        }

#pragma unroll
        for (int i = 0; i < 4; i++) {
            int qg = q0 + ty * 4 + i;
            int qgi = (qg - 1) >> 5;
            int qgj = (qg - 1) & 31;
#pragma unroll
            for (int j = 0; j < 4; j++) {
                int kg = kt + tx * 4 + j;
                float val = 0.f;
                if (kg < LSEQ && qg < LSEQ) {
                    float tm = 1.f;
                    if (qg != 0 && kg != 0) {
                        int ki = kg - 1;
                        int di = qgi - (ki >> 5) + 32;
                        int dj = qgj - (ki & 31) + 32;
                        tm = fabsf(tp[di * 64 + dj]);
                    }
                    val = s[i][j] * tm + EPSF;
                }
                st[(tx * 4 + j) * 68 + ty * 4 + i] = val;
                rs[i] += val;
            }
        }
        __syncthreads();

#pragma unroll 16
        for (int tk = 0; tk < 64; tk++) {
            float4 s4 = *(float4*)&st[tk * 68 + ty * 4];
            float4 v4 = *(float4*)&vs[tk * 68 + tx * 4];
            float sv[4] = {s4.x, s4.y, s4.z, s4.w};
            float vv[4] = {v4.x, v4.y, v4.z, v4.w};
#pragma unroll
            for (int i = 0; i < 4; i++)
#pragma unroll
                for (int j = 0; j < 4; j++)
                    outv[i][j] = fmaf(sv[i], vv[j], outv[i][j]);
        }
    }
    __syncthreads();

#pragma unroll
    for (int i = 0; i < 4; i++)
        st[(ty * 4 + i) * 17 + tx] = rs[i];
    __syncthreads();

#pragma unroll
    for (int i = 0; i < 4; i++) {
        int qg = q0 + ty * 4 + i;
        if (qg >= LSEQ) continue;
        float tot = 0.f;
#pragma unroll
        for (int t = 0; t < 16; t++) tot += st[(ty * 4 + i) * 17 + t];
        float inv = 1.f / tot;
        float4 o4 = make_float4(outv[i][0] * inv, outv[i][1] * inv,
                                outv[i][2] * inv, outv[i][3] * inv);
        *(float4*)&outp[((size_t)(b * LSEQ + qg)) * FEAT + h * DIM + tx * 4] = o4;
    }
}

// ---------------------------------------------------------------------------
extern "C" void kernel_launch(void* const* d_in, const int* in_sizes, int n_in,
                              void* d_out, int out_size)
{
    const float* x    = (const float*)d_in[0];
    const float* wq   = (const float*)d_in[1];
    const float* bq   = (const float*)d_in[2];
    const float* wk   = (const float*)d_in[3];
    const float* bk   = (const float*)d_in[4];
    const float* wv   = (const float*)d_in[5];
    const float* bv   = (const float*)d_in[6];
    const float* wo   = (const float*)d_in[7];
    const float* bo   = (const float*)d_in[8];
    const float* tpar = (const float*)d_in[9];
    float* out = (float*)d_out;

    float *qp, *kp, *vp, *op;
    cudaGetSymbolAddress((void**)&qp, g_q);
    cudaGetSymbolAddress((void**)&kp, g_k);
    cudaGetSymbolAddress((void**)&vp, g_v);
    cudaGetSymbolAddress((void**)&op, g_o);

    dim3 tg((MROWS + 127) / 128, FEAT / 128);   // 129 x 6
    tgemm<0><<<tg, 256>>>(x, wq, bq, qp);
    tgemm<1><<<tg, 256>>>(x, wk, bk, kp);
    tgemm<2><<<tg, 256>>>(x, wv, bv, vp);

    const int smem_bytes = (4096 + 4 * 64 * 68) * 4;  // 86016
    cudaFuncSetAttribute(attn_kernel, cudaFuncAttributeMaxDynamicSharedMemorySize,
                         smem_bytes);
    attn_kernel<<<dim3(17, HEADS, BATCH), 256, smem_bytes>>>(tpar, op);

    tgemm<3><<<tg, 256>>>(op, wo, bo, out);
}

// round 9
// speedup vs baseline: 1.7743x; 1.5816x over previous
#include <cuda_runtime.h>
#include <cstdint>

#define BATCH 16
#define HEADS 12
#define DIM 64
#define FEAT 768
#define LSEQ 1025
#define MROWS (BATCH * LSEQ)   // 16400
#define EPSF 1e-8f

// Scratch (allocation-free rule: __device__ globals)
__device__ float g_q[(size_t)BATCH * HEADS * LSEQ * DIM];
__device__ float g_k[(size_t)BATCH * HEADS * LSEQ * DIM];
__device__ float g_v[(size_t)BATCH * HEADS * LSEQ * DIM];
__device__ float g_o[(size_t)MROWS * FEAT];

// ---------------------------------------------------------------------------
// helpers
// ---------------------------------------------------------------------------
__device__ __forceinline__ uint32_t tf32(float f) {
    uint32_t u;
    asm("cvt.rna.tf32.f32 %0, %1;" : "=r"(u) : "f"(f));
    return u;
}
__device__ __forceinline__ void mma_tf32(float* d, const uint32_t* a,
                                         uint32_t b0, uint32_t b1) {
    asm volatile("mma.sync.aligned.m16n8k8.row.col.f32.tf32.tf32.f32 "
                 "{%0,%1,%2,%3}, {%4,%5,%6,%7}, {%8,%9}, {%0,%1,%2,%3};"
                 : "+f"(d[0]), "+f"(d[1]), "+f"(d[2]), "+f"(d[3])
                 : "r"(a[0]), "r"(a[1]), "r"(a[2]), "r"(a[3]),
                   "r"(b0), "r"(b1));
}

// ---------------------------------------------------------------------------
// tf32 GEMM: C = A[M,768] * W[768,768] + bias. CTA 128x128, BK=32,
// 8 warps (4x2), warp tile 32x64. smem A[m][k] stride 36, BT[n][k] stride 36.
// MODE 0: q=relu((acc+b)/8)+eps -> g_q[B][H][L][D]
// MODE 1: k=relu(acc+b)+eps     -> g_k
// MODE 2: v=acc+b               -> g_v
// MODE 3: out=acc+b             -> C row-major [M,768]
// ---------------------------------------------------------------------------
template <int MODE>
__global__ __launch_bounds__(256, 1) void tgemm(
    const float* __restrict__ A, const float* __restrict__ W,
    const float* __restrict__ bias, float* __restrict__ C)
{
    __shared__ __align__(16) uint32_t smA[128 * 36];
    __shared__ __align__(16) uint32_t smB[128 * 36];   // BT[n][k]

    const int tid = threadIdx.x;
    const int wid = tid >> 5, lane = tid & 31;
    const int g = lane >> 2, tq = lane & 3;
    const int m0 = blockIdx.x * 128, n0 = blockIdx.y * 128;

    const int mw = (wid >> 1) * 32;       // warp m offset
    const int nw = (wid & 1) * 64;        // warp n offset

    // A loader: row = tid>>1, 16-float half = (tid&1)*16
    const int ar = tid >> 1, ah16 = (tid & 1) * 16;
    const bool aval = (m0 + ar) < MROWS;
    const float* abase = A + (size_t)(m0 + ar) * FEAT + ah16;

    float acc[2][8][4];
#pragma unroll
    for (int i = 0; i < 2; i++)
#pragma unroll
        for (int j = 0; j < 8; j++)
#pragma unroll
            for (int q = 0; q < 4; q++) acc[i][j][q] = 0.f;

    for (int k0 = 0; k0 < FEAT; k0 += 32) {
        // ---- load A tile [128][32] ----
        {
            const float4* src = (const float4*)(abase + k0);
#pragma unroll
            for (int i = 0; i < 4; i++) {
                float4 v = aval ? src[i] : make_float4(0.f, 0.f, 0.f, 0.f);
                uint4 u = make_uint4(tf32(v.x), tf32(v.y), tf32(v.z), tf32(v.w));
                *(uint4*)&smA[ar * 36 + ah16 + i * 4] = u;
            }
        }
        // ---- load + transpose W tile [32][128] -> BT[n][k] ----
        {
#pragma unroll
            for (int t = 0; t < 2; t++) {
                const int id = t * 256 + tid;       // 512 items: 16 kpairs x 32 n4
                const int kp = id >> 5;             // 0..15
                const int n4 = (id & 31) << 2;      // 0..124
                const float* w0 = W + (size_t)(k0 + 2 * kp) * FEAT + n0 + n4;
                float4 r0 = *(const float4*)w0;
                float4 r1 = *(const float4*)(w0 + FEAT);
                const float e0[4] = {r0.x, r0.y, r0.z, r0.w};
                const float e1[4] = {r1.x, r1.y, r1.z, r1.w};
#pragma unroll
                for (int j = 0; j < 4; j++) {
                    uint2 u = make_uint2(tf32(e0[j]), tf32(e1[j]));
                    *(uint2*)&smB[(n4 + j) * 36 + 2 * kp] = u;
                }
            }
        }
        __syncthreads();

        // ---- mma: 4 k8 steps ----
#pragma unroll
        for (int ks = 0; ks < 4; ks++) {
            const int kd = ks * 8;
            uint32_t a[2][4];
#pragma unroll
            for (int mf = 0; mf < 2; mf++) {
                const int base = (mw + mf * 16 + g) * 36 + kd + tq;
                a[mf][0] = smA[base];
                a[mf][1] = smA[base + 8 * 36];
                a[mf][2] = smA[base + 4];
                a[mf][3] = smA[base + 8 * 36 + 4];
            }
#pragma unroll
            for (int nf = 0; nf < 8; nf++) {
                const int bb = (nw + nf * 8 + g) * 36 + kd + tq;
                const uint32_t b0 = smB[bb], b1 = smB[bb + 4];
                mma_tf32(acc[0][nf], a[0], b0, b1);
                mma_tf32(acc[1][nf], a[1], b0, b1);
            }
        }
        __syncthreads();
    }

    // ---- epilogue ----
#pragma unroll
    for (int mf = 0; mf < 2; mf++) {
#pragma unroll
        for (int half = 0; half < 2; half++) {
            const int r = m0 + mw + mf * 16 + g + half * 8;
            if (r >= MROWS) continue;
            int bb2 = 0, l = 0;
            if (MODE != 3) { bb2 = r / LSEQ; l = r - bb2 * LSEQ; }
#pragma unroll
            for (int nf = 0; nf < 8; nf++) {
                const int c = n0 + nw + nf * 8 + tq * 2;
                float v0 = acc[mf][nf][half * 2 + 0] + bias[c];
                float v1 = acc[mf][nf][half * 2 + 1] + bias[c + 1];
                if (MODE == 0) {
                    v0 = fmaxf(v0 * 0.125f, 0.f) + EPSF;
                    v1 = fmaxf(v1 * 0.125f, 0.f) + EPSF;
                } else if (MODE == 1) {
                    v0 = fmaxf(v0, 0.f) + EPSF;
                    v1 = fmaxf(v1, 0.f) + EPSF;
                }
                float2 o = make_float2(v0, v1);
                if (MODE == 3) {
                    *(float2*)&C[(size_t)r * FEAT + c] = o;
                } else {
                    const int h = c >> 6, d = c & 63;
                    *(float2*)&C[(((size_t)(bb2 * HEADS + h)) * LSEQ + l) * DIM + d] = o;
                }
            }
        }
    }
}

// ---------------------------------------------------------------------------
// Tensorized fused attention (tf32 mma).
// Block = (qtile 128, h, b). 8 warps: S tile 128q x 128k (warp 32x64),
// O tile 128q x 64d (warp 32x32).
// smem (floats): tp[4096] | Qs[128][68] | Ks[128][68] | Vt[64][129] |
//                Ps[128][132] | rssm[2][128]
// ---------------------------------------------------------------------------
#define QS_OFF 4096
#define KS_OFF (QS_OFF + 128 * 68)
#define VT_OFF (KS_OFF + 128 * 68)
#define PS_OFF (VT_OFF + 64 * 129)
#define RS_OFF (PS_OFF + 128 * 132)
#define ATT_SMEM ((RS_OFF + 256) * 4)

__global__ __launch_bounds__(256, 1) void attn_tf32(const float* __restrict__ tpar,
                                                    float* __restrict__ outp)
{
    extern __shared__ float sm[];
    float* tp = sm;
    uint32_t* Qs = (uint32_t*)(sm + QS_OFF);
    uint32_t* Ks = (uint32_t*)(sm + KS_OFF);
    uint32_t* Vt = (uint32_t*)(sm + VT_OFF);
    uint32_t* Ps = (uint32_t*)(sm + PS_OFF);
    float* rssm = sm + RS_OFF;

    const int tid = threadIdx.x;
    const int wid = tid >> 5, lane = tid & 31;
    const int g = lane >> 2, tq = lane & 3;
    const int q0 = blockIdx.x * 128;
    const int h = blockIdx.y;
    const int b = blockIdx.z;

    const int mw  = (wid >> 1) * 32;
    const int nwk = (wid & 1) * 64;
    const int nwd = (wid & 1) * 32;

    const float* qp = g_q + ((size_t)(b * HEADS + h)) * LSEQ * DIM;
    const float* kp = g_k + ((size_t)(b * HEADS + h)) * LSEQ * DIM;
    const float* vp = g_v + ((size_t)(b * HEADS + h)) * LSEQ * DIM;

    for (int i = tid; i < 4096; i += 256) tp[i] = tpar[h * 4096 + i];

    // ---- load Q tile [128][64] -> tf32 ----
#pragma unroll
    for (int i = 0; i < 8; i++) {
        const int idx = i * 256 + tid;
        const int r = idx >> 4, c4 = (idx & 15) << 2;
        const int qg = q0 + r;
        float4 v = (qg < LSEQ) ? *(const float4*)&qp[(size_t)qg * DIM + c4]
                               : make_float4(0.f, 0.f, 0.f, 0.f);
        *(uint4*)&Qs[r * 68 + c4] = make_uint4(tf32(v.x), tf32(v.y), tf32(v.z), tf32(v.w));
    }

    // per-thread row info
    int rowl[2][2], qgr[2][2], qir[2][2], qjr[2][2];
    bool vq[2][2];
#pragma unroll
    for (int mf = 0; mf < 2; mf++)
#pragma unroll
        for (int hf = 0; hf < 2; hf++) {
            const int rl = mw + mf * 16 + g + hf * 8;
            rowl[mf][hf] = rl;
            const int qg = q0 + rl;
            qgr[mf][hf] = qg;
            vq[mf][hf] = qg < LSEQ;
            qir[mf][hf] = (qg - 1) >> 5;
            qjr[mf][hf] = (qg - 1) & 31;
        }

    float acc_o[2][4][4];
#pragma unroll
    for (int i = 0; i < 2; i++)
#pragma unroll
        for (int j = 0; j < 4; j++)
#pragma unroll
            for (int q = 0; q < 4; q++) acc_o[i][j][q] = 0.f;
    float rs[2][2] = {{0.f, 0.f}, {0.f, 0.f}};

    for (int kt = 0; kt < 9; kt++) {
        const int ktb = kt * 128;
        __syncthreads();    // prev PV done (Vt/Ks reuse); first iter: Qs/tp ready

        // ---- load K [128][64] and V -> Vt[64][128] transposed ----
#pragma unroll
        for (int i = 0; i < 8; i++) {
            const int idx = i * 256 + tid;
            const int r = idx >> 4, c4 = (idx & 15) << 2;
            const int kg = ktb + r;
            float4 kv, vv;
            if (kg < LSEQ) {
                kv = *(const float4*)&kp[(size_t)kg * DIM + c4];
                vv = *(const float4*)&vp[(size_t)kg * DIM + c4];
            } else {
                kv = make_float4(0.f, 0.f, 0.f, 0.f);
                vv = kv;
            }
            *(uint4*)&Ks[r * 68 + c4] = make_uint4(tf32(kv.x), tf32(kv.y), tf32(kv.z), tf32(kv.w));
            Vt[(c4 + 0) * 129 + r] = tf32(vv.x);
            Vt[(c4 + 1) * 129 + r] = tf32(vv.y);
            Vt[(c4 + 2) * 129 + r] = tf32(vv.z);
            Vt[(c4 + 3) * 129 + r] = tf32(vv.w);
        }
        __syncthreads();

        // ---- S = Q.K^T over d=64 (8 k8 steps) ----
        float s_acc[2][8][4];
#pragma unroll
        for (int i = 0; i < 2; i++)
#pragma unroll
            for (int j = 0; j < 8; j++)
#pragma unroll
                for (int q = 0; q < 4; q++) s_acc[i][j][q] = 0.f;

#pragma unroll
        for (int ks = 0; ks < 8; ks++) {
            const int kd = ks * 8;
            uint32_t a[2][4];
#pragma unroll
            for (int mf = 0; mf < 2; mf++) {
                const int base = (mw + mf * 16 + g) * 68 + kd + tq;
                a[mf][0] = Qs[base];
                a[mf][1] = Qs[base + 8 * 68];
                a[mf][2] = Qs[base + 4];
                a[mf][3] = Qs[base + 8 * 68 + 4];
            }
#pragma unroll
            for (int nf = 0; nf < 8; nf++) {
                const int bb = (nwk + nf * 8 + g) * 68 + kd + tq;
                const uint32_t b0 = Ks[bb], b1 = Ks[bb + 4];
                mma_tf32(s_acc[0][nf], a[0], b0, b1);
                mma_tf32(s_acc[1][nf], a[1], b0, b1);
            }
        }

        // ---- mask + eps + rowsum, write P (tf32) ----
#pragma unroll
        for (int mf = 0; mf < 2; mf++) {
#pragma unroll
            for (int hf = 0; hf < 2; hf++) {
                const int qg = qgr[mf][hf];
                const bool vqq = vq[mf][hf];
                const int qi = qir[mf][hf], qj = qjr[mf][hf];
#pragma unroll
                for (int nf = 0; nf < 8; nf++) {
                    const int kl0 = nwk + nf * 8 + tq * 2;
                    float val[2];
#pragma unroll
                    for (int e = 0; e < 2; e++) {
                        const int kg = ktb + kl0 + e;
                        const float s = s_acc[mf][nf][hf * 2 + e];
                        const bool v = vqq && (kg < LSEQ);
                        float tm = 1.f;
                        if (v && qg != 0 && kg != 0) {
                            const int kk = kg - 1;
                            const int di = qi - (kk >> 5) + 32;
                            const int dj = qj - (kk & 31) + 32;
                            tm = fabsf(tp[di * 64 + dj]);
                        }
                        val[e] = v ? fmaf(s, tm, EPSF) : 0.f;
                    }
                    rs[mf][hf] += val[0] + val[1];
                    *(uint2*)&Ps[rowl[mf][hf] * 132 + kl0] =
                        make_uint2(tf32(val[0]), tf32(val[1]));
                }
            }
        }
        __syncthreads();

        // ---- O += P.V (16 k8 steps over ktok) ----
#pragma unroll
        for (int s = 0; s < 16; s++) {
            const int kk = s * 8;
            uint32_t a[2][4];
#pragma unroll
            for (int mf = 0; mf < 2; mf++) {
                const int base = (mw + mf * 16 + g) * 132 + kk + tq;
                a[mf][0] = Ps[base];
                a[mf][1] = Ps[base + 8 * 132];
                a[mf][2] = Ps[base + 4];
                a[mf][3] = Ps[base + 8 * 132 + 4];
            }
#pragma unroll
            for (int nf = 0; nf < 4; nf++) {
                const int bb = (nwd + nf * 8 + g) * 129 + kk + tq;
                const uint32_t b0 = Vt[bb], b1 = Vt[bb + 4];
                mma_tf32(acc_o[0][nf], a[0], b0, b1);
                mma_tf32(acc_o[1][nf], a[1], b0, b1);
            }
        }
    }
    __syncthreads();

    // ---- rowsum reduction ----
#pragma unroll
    for (int mf = 0; mf < 2; mf++)
#pragma unroll
        for (int hf = 0; hf < 2; hf++) {
            float v = rs[mf][hf];
            v += __shfl_xor_sync(0xffffffffu, v, 1);
            v += __shfl_xor_sync(0xffffffffu, v, 2);
            if (tq == 0) rssm[(wid & 1) * 128 + rowl[mf][hf]] = v;
        }
    __syncthreads();

    // ---- normalize + write ----
#pragma unroll
    for (int mf = 0; mf < 2; mf++) {
#pragma unroll
        for (int hf = 0; hf < 2; hf++) {
            const int qg = qgr[mf][hf];
            if (qg >= LSEQ) continue;
            const int rl = rowl[mf][hf];
            const float inv = 1.f / (rssm[rl] + rssm[128 + rl]);
            float* dst = outp + (size_t)(b * LSEQ + qg) * FEAT + h * 64;
#pragma unroll
            for (int nf = 0; nf < 4; nf++) {
                const int d0 = nwd + nf * 8 + tq * 2;
                float2 o = make_float2(acc_o[mf][nf][hf * 2 + 0] * inv,
                                       acc_o[mf][nf][hf * 2 + 1] * inv);
                *(float2*)&dst[d0] = o;
            }
        }
    }
}

// ---------------------------------------------------------------------------
extern "C" void kernel_launch(void* const* d_in, const int* in_sizes, int n_in,
                              void* d_out, int out_size)
{
    const float* x    = (const float*)d_in[0];
    const float* wq   = (const float*)d_in[1];
    const float* bq   = (const float*)d_in[2];
    const float* wk   = (const float*)d_in[3];
    const float* bk   = (const float*)d_in[4];
    const float* wv   = (const float*)d_in[5];
    const float* bv   = (const float*)d_in[6];
    const float* wo   = (const float*)d_in[7];
    const float* bo   = (const float*)d_in[8];
    const float* tpar = (const float*)d_in[9];
    float* out = (float*)d_out;

    float *qp, *kp, *vp, *op;
    cudaGetSymbolAddress((void**)&qp, g_q);
    cudaGetSymbolAddress((void**)&kp, g_k);
    cudaGetSymbolAddress((void**)&vp, g_v);
    cudaGetSymbolAddress((void**)&op, g_o);

    dim3 tg((MROWS + 127) / 128, FEAT / 128);   // 129 x 6
    tgemm<0><<<tg, 256>>>(x, wq, bq, qp);
    tgemm<1><<<tg, 256>>>(x, wk, bk, kp);
    tgemm<2><<<tg, 256>>>(x, wv, bv, vp);

    cudaFuncSetAttribute(attn_tf32, cudaFuncAttributeMaxDynamicSharedMemorySize,
                         ATT_SMEM);
    attn_tf32<<<dim3(9, HEADS, BATCH), 256, ATT_SMEM>>>(tpar, op);

    tgemm<3><<<tg, 256>>>(op, wo, bo, out);
}

// round 12
// speedup vs baseline: 2.0393x; 1.1494x over previous
#include <cuda_runtime.h>
#include <cstdint>

#define BATCH 16
#define HEADS 12
#define DIM 64
#define FEAT 768
#define LSEQ 1025
#define MROWS (BATCH * LSEQ)   // 16400
#define EPSF 1e-8f

// Scratch (allocation-free rule: __device__ globals)
__device__ float g_q[(size_t)BATCH * HEADS * LSEQ * DIM];
__device__ float g_k[(size_t)BATCH * HEADS * LSEQ * DIM];
__device__ float g_v[(size_t)BATCH * HEADS * LSEQ * DIM];
__device__ float g_o[(size_t)MROWS * FEAT];
__device__ float g_x[(size_t)MROWS * FEAT];          // tf32-rounded X
__device__ float g_wt[4][(size_t)FEAT * FEAT];       // tf32-rounded W^T [n][k]

// ---------------------------------------------------------------------------
// helpers
// ---------------------------------------------------------------------------
__device__ __forceinline__ uint32_t smem_u32(const void* p) {
    uint32_t a;
    asm("{ .reg .u64 t; cvta.to.shared.u64 t, %1; cvt.u32.u64 %0, t; }"
        : "=r"(a) : "l"(p));
    return a;
}
__device__ __forceinline__ uint32_t tf32u(float f) {
    uint32_t u;
    asm("cvt.rna.tf32.f32 %0, %1;" : "=r"(u) : "f"(f));
    return u;
}
__device__ __forceinline__ float tf32f(float f) {
    return __uint_as_float(tf32u(f));
}
__device__ __forceinline__ void mma_tf32(float* d, const uint32_t* a,
                                         uint32_t b0, uint32_t b1) {
    asm volatile("mma.sync.aligned.m16n8k8.row.col.f32.tf32.tf32.f32 "
                 "{%0,%1,%2,%3}, {%4,%5,%6,%7}, {%8,%9}, {%0,%1,%2,%3};"
                 : "+f"(d[0]), "+f"(d[1]), "+f"(d[2]), "+f"(d[3])
                 : "r"(a[0]), "r"(a[1]), "r"(a[2]), "r"(a[3]),
                   "r"(b0), "r"(b1));
}
__device__ __forceinline__ void cp16(uint32_t dst, const void* src, bool v) {
    int sz = v ? 16 : 0;
    asm volatile("cp.async.cg.shared.global [%0], [%1], 16, %2;"
                 :: "r"(dst), "l"(src), "r"(sz) : "memory");
}
#define CP_COMMIT() asm volatile("cp.async.commit_group;" ::: "memory")
#define CP_WAIT1()  asm volatile("cp.async.wait_group 1;" ::: "memory")
#define CP_WAIT0()  asm volatile("cp.async.wait_group 0;" ::: "memory")

// ---------------------------------------------------------------------------
// prepasses
// ---------------------------------------------------------------------------
__global__ void xconv(const float* __restrict__ X, float* __restrict__ XO) {
    const int i = blockIdx.x * 256 + threadIdx.x;   // float4 index
    float4 v = ((const float4*)X)[i];
    float4 o = make_float4(tf32f(v.x), tf32f(v.y), tf32f(v.z), tf32f(v.w));
    ((float4*)XO)[i] = o;
}
// W[k][n] (768x768 row-major) -> WT[n][k] tf32-rounded
__global__ void wtrans(const float* __restrict__ W, float* __restrict__ WT) {
    __shared__ float t[32][33];
    const int k0 = blockIdx.x * 32, n0 = blockIdx.y * 32;
    const int x = threadIdx.x, y = threadIdx.y;    // 32 x 8
#pragma unroll
    for (int i = y; i < 32; i += 8)
        t[i][x] = W[(size_t)(k0 + i) * FEAT + n0 + x];
    __syncthreads();
#pragma unroll
    for (int i = y; i < 32; i += 8)
        WT[(size_t)(n0 + i) * FEAT + k0 + x] = tf32f(t[x][i]);
}

// ---------------------------------------------------------------------------
// Pipelined tf32 GEMM: C = A[M,768] * W + bias, A and WT pre-tf32-rounded.
// CTA 128x128, BK=32, cp.async double-buffered, 8 warps (4x2), warp 32x64.
// smem per buf: A[128][36] | BT[128][36] (floats); 2 bufs = 73728 B dynamic.
// MODE 0: q=relu((acc+b)/8)+eps (tf32-rounded) -> g_q[B][H][L][D]
// MODE 1: k=relu(acc+b)+eps (tf32)             -> g_k
// MODE 2: v=acc+b (tf32)                       -> g_v
// MODE 3: out=acc+b                            -> C row-major [M,768]
// ---------------------------------------------------------------------------
#define TG_BUF 9216               // floats per buffer (A 4608 + B 4608)
#define TG_SMEM (2 * TG_BUF * 4)  // 73728 bytes

template <int MODE>
__global__ __launch_bounds__(256, 2) void tgemm(
    const float* __restrict__ A, const float* __restrict__ WT,
    const float* __restrict__ bias, float* __restrict__ C)
{
    extern __shared__ uint32_t smg[];
    const int tid = threadIdx.x;
    const int wid = tid >> 5, lane = tid & 31;
    const int g = lane >> 2, tq = lane & 3;
    const int m0 = blockIdx.x * 128, n0 = blockIdx.y * 128;
    const int mw = (wid >> 1) * 32, nw = (wid & 1) * 64;

    const uint32_t sbase = smem_u32(smg);
    const int ar = tid >> 1, half = (tid & 1) * 16;
    const bool aval = (m0 + ar) < MROWS;
    const float* asrc = A + (size_t)(m0 + ar) * FEAT + half;
    const float* bsrc = WT + (size_t)(n0 + ar) * FEAT + half;
    const uint32_t soffA = (uint32_t)(ar * 36 + half) * 4;
    const uint32_t soffB = soffA + 4608u * 4;

    float acc[2][8][4];
#pragma unroll
    for (int i = 0; i < 2; i++)
#pragma unroll
        for (int j = 0; j < 8; j++)
#pragma unroll
            for (int q = 0; q < 4; q++) acc[i][j][q] = 0.f;

    // prologue: stage 0
    {
        const int k0 = 0;
#pragma unroll
        for (int j = 0; j < 4; j++) {
            cp16(sbase + soffA + 16u * j, asrc + k0 + 4 * j, aval);
            cp16(sbase + soffB + 16u * j, bsrc + k0 + 4 * j, true);
        }
        CP_COMMIT();
    }

#pragma unroll 1
    for (int s = 0; s < 24; s++) {
        const uint32_t bufo = (uint32_t)(s & 1) * TG_BUF;
        if (s + 1 < 24) {
            const uint32_t nbo = (uint32_t)((s + 1) & 1) * TG_BUF * 4;
            const int k0 = (s + 1) * 32;
#pragma unroll
            for (int j = 0; j < 4; j++) {
                cp16(sbase + nbo + soffA + 16u * j, asrc + k0 + 4 * j, aval);
                cp16(sbase + nbo + soffB + 16u * j, bsrc + k0 + 4 * j, true);
            }
            CP_COMMIT();
            CP_WAIT1();
        } else {
            CP_WAIT0();
        }
        __syncthreads();

        const uint32_t* smA = smg + bufo;
        const uint32_t* smB = smg + bufo + 4608;
#pragma unroll
        for (int ks = 0; ks < 4; ks++) {
            const int kd = ks * 8;
            uint32_t a[2][4];
#pragma unroll
            for (int mf = 0; mf < 2; mf++) {
                const int base = (mw + mf * 16 + g) * 36 + kd + tq;
                a[mf][0] = smA[base];
                a[mf][1] = smA[base + 8 * 36];
                a[mf][2] = smA[base + 4];
                a[mf][3] = smA[base + 8 * 36 + 4];
            }
#pragma unroll
            for (int nf = 0; nf < 8; nf++) {
                const int bb = (nw + nf * 8 + g) * 36 + kd + tq;
                const uint32_t b0 = smB[bb], b1 = smB[bb + 4];
                mma_tf32(acc[0][nf], a[0], b0, b1);
                mma_tf32(acc[1][nf], a[1], b0, b1);
            }
        }
        __syncthreads();
    }

    // ---- epilogue ----
#pragma unroll
    for (int mf = 0; mf < 2; mf++) {
#pragma unroll
        for (int hf = 0; hf < 2; hf++) {
            const int r = m0 + mw + mf * 16 + g + hf * 8;
            if (r >= MROWS) continue;
            int bb2 = 0, l = 0;
            if (MODE != 3) { bb2 = r / LSEQ; l = r - bb2 * LSEQ; }
#pragma unroll
            for (int nf = 0; nf < 8; nf++) {
                const int c = n0 + nw + nf * 8 + tq * 2;
                float v0 = acc[mf][nf][hf * 2 + 0] + bias[c];
                float v1 = acc[mf][nf][hf * 2 + 1] + bias[c + 1];
                if (MODE == 0) {
                    v0 = tf32f(fmaxf(v0 * 0.125f, 0.f) + EPSF);
                    v1 = tf32f(fmaxf(v1 * 0.125f, 0.f) + EPSF);
                } else if (MODE == 1) {
                    v0 = tf32f(fmaxf(v0, 0.f) + EPSF);
                    v1 = tf32f(fmaxf(v1, 0.f) + EPSF);
                } else if (MODE == 2) {
                    v0 = tf32f(v0);
                    v1 = tf32f(v1);
                }
                float2 o = make_float2(v0, v1);
                if (MODE == 3) {
                    *(float2*)&C[(size_t)r * FEAT + c] = o;
                } else {
                    const int h = c >> 6, d = c & 63;
                    *(float2*)&C[(((size_t)(bb2 * HEADS + h)) * LSEQ + l) * DIM + d] = o;
                }
            }
        }
    }
}

// ---------------------------------------------------------------------------
// Fused attention, warp-strip layout.
// Block = (128 q, h, b); warp w owns q rows [w*16, w*16+16), full 128 k.
// Q frags in regs (loaded once), S in regs, P->PV via warp shuffles.
// smem floats: tp[4096] | Ks[128][68] | Vt[64][131]
// ---------------------------------------------------------------------------
#define KS_OFF 4096
#define VT_OFF (KS_OFF + 128 * 68)
#define ATT_SMEM ((VT_OFF + 64 * 131) * 4)   // 84736 B

__global__ __launch_bounds__(256, 1) void attn_tf32(const float* __restrict__ tpar,
                                                    float* __restrict__ outp)
{
    extern __shared__ float sma[];
    float* tp = sma;
    uint32_t* Ks = (uint32_t*)(sma + KS_OFF);
    uint32_t* Vt = (uint32_t*)(sma + VT_OFF);

    const int tid = threadIdx.x;
    const int wid = tid >> 5, lane = tid & 31;
    const int g = lane >> 2, tq = lane & 3;
    const int q0 = blockIdx.x * 128;
    const int h = blockIdx.y;
    const int b = blockIdx.z;

    const float* qp = g_q + ((size_t)(b * HEADS + h)) * LSEQ * DIM;
    const float* kp = g_k + ((size_t)(b * HEADS + h)) * LSEQ * DIM;
    const float* vp = g_v + ((size_t)(b * HEADS + h)) * LSEQ * DIM;

    for (int i = tid; i < 4096; i += 256) tp[i] = tpar[h * 4096 + i];

    // ---- stage Q into Ks, extract frags to registers ----
#pragma unroll
    for (int i = 0; i < 8; i++) {
        const int idx = i * 256 + tid;
        const int r = idx >> 4, c4 = (idx & 15) << 2;
        const int qg = q0 + r;
        uint4 v = (qg < LSEQ) ? *(const uint4*)&qp[(size_t)qg * DIM + c4]
                              : make_uint4(0u, 0u, 0u, 0u);
        *(uint4*)&Ks[r * 68 + c4] = v;
    }
    __syncthreads();

    const int rowlo = wid * 16 + g;
    uint32_t qf[8][4];
#pragma unroll
    for (int ks = 0; ks < 8; ks++) {
        const int base = rowlo * 68 + ks * 8 + tq;
        qf[ks][0] = Ks[base];
        qf[ks][1] = Ks[base + 8 * 68];
        qf[ks][2] = Ks[base + 4];
        qf[ks][3] = Ks[base + 8 * 68 + 4];
    }

    const int qg_lo = q0 + rowlo, qg_hi = qg_lo + 8;
    const bool vq_lo = qg_lo < LSEQ, vq_hi = qg_hi < LSEQ;
    const int qi_lo = (qg_lo - 1) >> 5, qj_lo = (qg_lo - 1) & 31;
    const int qi_hi = (qg_hi - 1) >> 5, qj_hi = (qg_hi - 1) & 31;

    float acc_o[8][4];
#pragma unroll
    for (int j = 0; j < 8; j++)
#pragma unroll
        for (int q = 0; q < 4; q++) acc_o[j][q] = 0.f;
    float rs0 = 0.f, rs1 = 0.f;

#pragma unroll 1
    for (int kt = 0; kt < 9; kt++) {
        const int ktb = kt * 128;
        __syncthreads();   // Ks/Vt reuse guard (first iter: qf extraction done)

        // ---- load K [128][64] raw, V -> Vt[64][131] transposed ----
#pragma unroll
        for (int i = 0; i < 8; i++) {
            const int idx = i * 256 + tid;
            const int r = idx >> 4, c4 = (idx & 15) << 2;
            const int kg = ktb + r;
            uint4 kv, vv;
            if (kg < LSEQ) {
                kv = *(const uint4*)&kp[(size_t)kg * DIM + c4];
                vv = *(const uint4*)&vp[(size_t)kg * DIM + c4];
            } else {
                kv = make_uint4(0u, 0u, 0u, 0u);
                vv = kv;
            }
            *(uint4*)&Ks[r * 68 + c4] = kv;
            Vt[(c4 + 0) * 131 + r] = vv.x;
            Vt[(c4 + 1) * 131 + r] = vv.y;
            Vt[(c4 + 2) * 131 + r] = vv.z;
            Vt[(c4 + 3) * 131 + r] = vv.w;
        }
        __syncthreads();

        // ---- S = Q.K^T : 16 rows x 128 cols per warp ----
        float s_acc[16][4];
#pragma unroll
        for (int j = 0; j < 16; j++)
#pragma unroll
            for (int q = 0; q < 4; q++) s_acc[j][q] = 0.f;
#pragma unroll
        for (int ks = 0; ks < 8; ks++) {
            const int kd = ks * 8;
#pragma unroll
            for (int nf = 0; nf < 16; nf++) {
                const int bb = (nf * 8 + g) * 68 + kd + tq;
                mma_tf32(s_acc[nf], qf[ks], Ks[bb], Ks[bb + 4]);
            }
        }

        // ---- mask + eps + rowsum -> P (tf32 bits in regs) ----
        uint32_t p[16][4];
#pragma unroll
        for (int nf = 0; nf < 16; nf++) {
            const int kl0 = nf * 8 + 2 * tq;
#pragma unroll
            for (int e = 0; e < 2; e++) {
                const int kg = ktb + kl0 + e;
                const bool kvld = kg < LSEQ;
                const int kk = kg - 1;
                const int kki = kk >> 5, kkj = kk & 31;
                float vlo = 0.f;
                if (vq_lo && kvld) {
                    float tm = 1.f;
                    if (qg_lo != 0 && kg != 0)
                        tm = fabsf(tp[(qi_lo - kki + 32) * 64 + (qj_lo - kkj + 32)]);
                    vlo = fmaf(s_acc[nf][e], tm, EPSF);
                }
                float vhi = 0.f;
                if (vq_hi && kvld) {
                    float tm = 1.f;
                    if (kg != 0)   // qg_hi >= 8, never CLS
                        tm = fabsf(tp[(qi_hi - kki + 32) * 64 + (qj_hi - kkj + 32)]);
                    vhi = fmaf(s_acc[nf][2 + e], tm, EPSF);
                }
                rs0 += vlo;
                rs1 += vhi;
                p[nf][e] = tf32u(vlo);
                p[nf][2 + e] = tf32u(vhi);
            }
        }

        // ---- O += P.V : shuffle P into A-fragments ----
        const int lbase = lane & 28;
        const int slo = lbase | (tq >> 1);
        const int shi = slo + 2;
        const bool odd = (tq & 1);
#pragma unroll
        for (int s = 0; s < 16; s++) {
            uint32_t a[4];
            uint32_t e0 = __shfl_sync(0xffffffffu, p[s][0], slo);
            uint32_t e1 = __shfl_sync(0xffffffffu, p[s][1], slo);
            a[0] = odd ? e1 : e0;
            e0 = __shfl_sync(0xffffffffu, p[s][0], shi);
            e1 = __shfl_sync(0xffffffffu, p[s][1], shi);
            a[2] = odd ? e1 : e0;
            e0 = __shfl_sync(0xffffffffu, p[s][2], slo);
            e1 = __shfl_sync(0xffffffffu, p[s][3], slo);
            a[1] = odd ? e1 : e0;
            e0 = __shfl_sync(0xffffffffu, p[s][2], shi);
            e1 = __shfl_sync(0xffffffffu, p[s][3], shi);
            a[3] = odd ? e1 : e0;
#pragma unroll
            for (int nf = 0; nf < 8; nf++) {
                const int bb = (nf * 8 + g) * 131 + s * 8 + tq;
                mma_tf32(acc_o[nf], a, Vt[bb], Vt[bb + 4]);
            }
        }
    }

    // ---- rowsum reduce within quads (rows are warp-exclusive) ----
    rs0 += __shfl_xor_sync(0xffffffffu, rs0, 1);
    rs0 += __shfl_xor_sync(0xffffffffu, rs0, 2);
    rs1 += __shfl_xor_sync(0xffffffffu, rs1, 1);
    rs1 += __shfl_xor_sync(0xffffffffu, rs1, 2);

    // ---- normalize + write (tf32-rounded for the pre-rounded WO GEMM) ----
    if (vq_lo) {
        const float inv = 1.f / rs0;
        float* dst = outp + (size_t)(b * LSEQ + qg_lo) * FEAT + h * 64;
#pragma unroll
        for (int nf = 0; nf < 8; nf++) {
            const int d0 = nf * 8 + 2 * tq;
            *(float2*)&dst[d0] = make_float2(tf32f(acc_o[nf][0] * inv),
                                             tf32f(acc_o[nf][1] * inv));
        }
    }
    if (vq_hi) {
        const float inv = 1.f / rs1;
        float* dst = outp + (size_t)(b * LSEQ + qg_hi) * FEAT + h * 64;
#pragma unroll
        for (int nf = 0; nf < 8; nf++) {
            const int d0 = nf * 8 + 2 * tq;
            *(float2*)&dst[d0] = make_float2(tf32f(acc_o[nf][2] * inv),
                                             tf32f(acc_o[nf][3] * inv));
        }
    }
}

// ---------------------------------------------------------------------------
extern "C" void kernel_launch(void* const* d_in, const int* in_sizes, int n_in,
                              void* d_out, int out_size)
{
    const float* x    = (const float*)d_in[0];
    const float* wq   = (const float*)d_in[1];
    const float* bq   = (const float*)d_in[2];
    const float* wk   = (const float*)d_in[3];
    const float* bk   = (const float*)d_in[4];
    const float* wv   = (const float*)d_in[5];
    const float* bv   = (const float*)d_in[6];
    const float* wo   = (const float*)d_in[7];
    const float* bo   = (const float*)d_in[8];
    const float* tpar = (const float*)d_in[9];
    float* out = (float*)d_out;

    float *qp, *kp, *vp, *op, *xp, *wtp;
    cudaGetSymbolAddress((void**)&qp, g_q);
    cudaGetSymbolAddress((void**)&kp, g_k);
    cudaGetSymbolAddress((void**)&vp, g_v);
    cudaGetSymbolAddress((void**)&op, g_o);
    cudaGetSymbolAddress((void**)&xp, g_x);
    cudaGetSymbolAddress((void**)&wtp, g_wt);

    // prepasses: round X to tf32; transpose+round all weights
    xconv<<<(MROWS * FEAT) / (4 * 256), 256>>>(x, xp);
    dim3 wg(FEAT / 32, FEAT / 32), wb(32, 8);
    wtrans<<<wg, wb>>>(wq, wtp + 0 * (size_t)FEAT * FEAT);
    wtrans<<<wg, wb>>>(wk, wtp + 1 * (size_t)FEAT * FEAT);
    wtrans<<<wg, wb>>>(wv, wtp + 2 * (size_t)FEAT * FEAT);
    wtrans<<<wg, wb>>>(wo, wtp + 3 * (size_t)FEAT * FEAT);

    cudaFuncSetAttribute(tgemm<0>, cudaFuncAttributeMaxDynamicSharedMemorySize, TG_SMEM);
    cudaFuncSetAttribute(tgemm<1>, cudaFuncAttributeMaxDynamicSharedMemorySize, TG_SMEM);
    cudaFuncSetAttribute(tgemm<2>, cudaFuncAttributeMaxDynamicSharedMemorySize, TG_SMEM);
    cudaFuncSetAttribute(tgemm<3>, cudaFuncAttributeMaxDynamicSharedMemorySize, TG_SMEM);

    dim3 tg((MROWS + 127) / 128, FEAT / 128);   // 129 x 6
    tgemm<0><<<tg, 256, TG_SMEM>>>(xp, wtp + 0 * (size_t)FEAT * FEAT, bq, qp);
    tgemm<1><<<tg, 256, TG_SMEM>>>(xp, wtp + 1 * (size_t)FEAT * FEAT, bk, kp);
    tgemm<2><<<tg, 256, TG_SMEM>>>(xp, wtp + 2 * (size_t)FEAT * FEAT, bv, vp);

    cudaFuncSetAttribute(attn_tf32, cudaFuncAttributeMaxDynamicSharedMemorySize,
                         ATT_SMEM);
    attn_tf32<<<dim3(9, HEADS, BATCH), 256, ATT_SMEM>>>(tpar, op);

    tgemm<3><<<tg, 256, TG_SMEM>>>(op, wtp + 3 * (size_t)FEAT * FEAT, bo, out);
}

// round 15
// speedup vs baseline: 2.4508x; 1.2017x over previous
#include <cuda_runtime.h>
#include <cstdint>

#define BATCH 16
#define HEADS 12
#define DIM 64
#define FEAT 768
#define LSEQ 1025
#define MROWS (BATCH * LSEQ)   // 16400
#define EPSF 1e-8f

// Scratch (allocation-free rule: __device__ globals)
__device__ float g_q[(size_t)BATCH * HEADS * LSEQ * DIM];
__device__ float g_k[(size_t)BATCH * HEADS * LSEQ * DIM];
__device__ float g_v[(size_t)BATCH * HEADS * LSEQ * DIM];
__device__ float g_o[(size_t)MROWS * FEAT];
__device__ float g_x[(size_t)MROWS * FEAT];          // tf32-rounded X
__device__ float g_wt[4][(size_t)FEAT * FEAT];       // tf32-rounded W^T [n][k]

// ---------------------------------------------------------------------------
// helpers
// ---------------------------------------------------------------------------
__device__ __forceinline__ uint32_t smem_u32(const void* p) {
    uint32_t a;
    asm("{ .reg .u64 t; cvta.to.shared.u64 t, %1; cvt.u32.u64 %0, t; }"
        : "=r"(a) : "l"(p));
    return a;
}
__device__ __forceinline__ uint32_t tf32u(float f) {
    uint32_t u;
    asm("cvt.rna.tf32.f32 %0, %1;" : "=r"(u) : "f"(f));
    return u;
}
__device__ __forceinline__ float tf32f(float f) {
    return __uint_as_float(tf32u(f));
}
__device__ __forceinline__ void mma_tf32(float* d, const uint32_t* a,
                                         uint32_t b0, uint32_t b1) {
    asm volatile("mma.sync.aligned.m16n8k8.row.col.f32.tf32.tf32.f32 "
                 "{%0,%1,%2,%3}, {%4,%5,%6,%7}, {%8,%9}, {%0,%1,%2,%3};"
                 : "+f"(d[0]), "+f"(d[1]), "+f"(d[2]), "+f"(d[3])
                 : "r"(a[0]), "r"(a[1]), "r"(a[2]), "r"(a[3]),
                   "r"(b0), "r"(b1));
}
__device__ __forceinline__ void cp16(uint32_t dst, const void* src, bool v) {
    int sz = v ? 16 : 0;
    asm volatile("cp.async.cg.shared.global [%0], [%1], 16, %2;"
                 :: "r"(dst), "l"(src), "r"(sz) : "memory");
}
#define CP_COMMIT() asm volatile("cp.async.commit_group;" ::: "memory")
#define CP_WAIT1()  asm volatile("cp.async.wait_group 1;" ::: "memory")
#define CP_WAIT0()  asm volatile("cp.async.wait_group 0;" ::: "memory")

// ---------------------------------------------------------------------------
// prepasses
// ---------------------------------------------------------------------------
__global__ void xconv(const float* __restrict__ X, float* __restrict__ XO) {
    const int i = blockIdx.x * 256 + threadIdx.x;   // float4 index
    float4 v = ((const float4*)X)[i];
    float4 o = make_float4(tf32f(v.x), tf32f(v.y), tf32f(v.z), tf32f(v.w));
    ((float4*)XO)[i] = o;
}
// W[k][n] (768x768 row-major) -> WT[n][k] tf32-rounded
__global__ void wtrans(const float* __restrict__ W, float* __restrict__ WT) {
    __shared__ float t[32][33];
    const int k0 = blockIdx.x * 32, n0 = blockIdx.y * 32;
    const int x = threadIdx.x, y = threadIdx.y;    // 32 x 8
#pragma unroll
    for (int i = y; i < 32; i += 8)
        t[i][x] = W[(size_t)(k0 + i) * FEAT + n0 + x];
    __syncthreads();
#pragma unroll
    for (int i = y; i < 32; i += 8)
        WT[(size_t)(n0 + i) * FEAT + k0 + x] = tf32f(t[x][i]);
}

// ---------------------------------------------------------------------------
// Pipelined tf32 GEMM: C = A[M,768] * W + bias, A and WT pre-tf32-rounded.
// CTA 128x128, BK=32, cp.async double-buffered, 8 warps (4x2), warp 32x64.
// ---------------------------------------------------------------------------
#define TG_BUF 9216               // floats per buffer (A 4608 + B 4608)
#define TG_SMEM (2 * TG_BUF * 4)  // 73728 bytes

template <int MODE>
__global__ __launch_bounds__(256, 2) void tgemm(
    const float* __restrict__ A, const float* __restrict__ WT,
    const float* __restrict__ bias, float* __restrict__ C)
{
    extern __shared__ uint32_t smg[];
    const int tid = threadIdx.x;
    const int wid = tid >> 5, lane = tid & 31;
    const int g = lane >> 2, tq = lane & 3;
    const int m0 = blockIdx.x * 128, n0 = blockIdx.y * 128;
    const int mw = (wid >> 1) * 32, nw = (wid & 1) * 64;

    const uint32_t sbase = smem_u32(smg);
    const int ar = tid >> 1, half = (tid & 1) * 16;
    const bool aval = (m0 + ar) < MROWS;
    const float* asrc = A + (size_t)(m0 + ar) * FEAT + half;
    const float* bsrc = WT + (size_t)(n0 + ar) * FEAT + half;
    const uint32_t soffA = (uint32_t)(ar * 36 + half) * 4;
    const uint32_t soffB = soffA + 4608u * 4;

    float acc[2][8][4];
#pragma unroll
    for (int i = 0; i < 2; i++)
#pragma unroll
        for (int j = 0; j < 8; j++)
#pragma unroll
            for (int q = 0; q < 4; q++) acc[i][j][q] = 0.f;

    // prologue: stage 0
    {
#pragma unroll
        for (int j = 0; j < 4; j++) {
            cp16(sbase + soffA + 16u * j, asrc + 4 * j, aval);
            cp16(sbase + soffB + 16u * j, bsrc + 4 * j, true);
        }
        CP_COMMIT();
    }

#pragma unroll 1
    for (int s = 0; s < 24; s++) {
        const uint32_t bufo = (uint32_t)(s & 1) * TG_BUF;
        if (s + 1 < 24) {
            const uint32_t nbo = (uint32_t)((s + 1) & 1) * TG_BUF * 4;
            const int k0 = (s + 1) * 32;
#pragma unroll
            for (int j = 0; j < 4; j++) {
                cp16(sbase + nbo + soffA + 16u * j, asrc + k0 + 4 * j, aval);
                cp16(sbase + nbo + soffB + 16u * j, bsrc + k0 + 4 * j, true);
            }
            CP_COMMIT();
            CP_WAIT1();
        } else {
            CP_WAIT0();
        }
        __syncthreads();

        const uint32_t* smA = smg + bufo;
        const uint32_t* smB = smg + bufo + 4608;
#pragma unroll
        for (int ks = 0; ks < 4; ks++) {
            const int kd = ks * 8;
            uint32_t a[2][4];
#pragma unroll
            for (int mf = 0; mf < 2; mf++) {
                const int base = (mw + mf * 16 + g) * 36 + kd + tq;
                a[mf][0] = smA[base];
                a[mf][1] = smA[base + 8 * 36];
                a[mf][2] = smA[base + 4];
                a[mf][3] = smA[base + 8 * 36 + 4];
            }
#pragma unroll
            for (int nf = 0; nf < 8; nf++) {
                const int bb = (nw + nf * 8 + g) * 36 + kd + tq;
                const uint32_t b0 = smB[bb], b1 = smB[bb + 4];
                mma_tf32(acc[0][nf], a[0], b0, b1);
                mma_tf32(acc[1][nf], a[1], b0, b1);
            }
        }
        __syncthreads();
    }

    // ---- epilogue ----
#pragma unroll
    for (int mf = 0; mf < 2; mf++) {
#pragma unroll
        for (int hf = 0; hf < 2; hf++) {
            const int r = m0 + mw + mf * 16 + g + hf * 8;
            if (r >= MROWS) continue;
            int bb2 = 0, l = 0;
            if (MODE != 3) { bb2 = r / LSEQ; l = r - bb2 * LSEQ; }
#pragma unroll
            for (int nf = 0; nf < 8; nf++) {
                const int c = n0 + nw + nf * 8 + tq * 2;
                float v0 = acc[mf][nf][hf * 2 + 0] + bias[c];
                float v1 = acc[mf][nf][hf * 2 + 1] + bias[c + 1];
                if (MODE == 0) {
                    v0 = tf32f(fmaxf(v0 * 0.125f, 0.f) + EPSF);
                    v1 = tf32f(fmaxf(v1 * 0.125f, 0.f) + EPSF);
                } else if (MODE == 1) {
                    v0 = tf32f(fmaxf(v0, 0.f) + EPSF);
                    v1 = tf32f(fmaxf(v1, 0.f) + EPSF);
                } else if (MODE == 2) {
                    v0 = tf32f(v0);
                    v1 = tf32f(v1);
                }
                float2 o = make_float2(v0, v1);
                if (MODE == 3) {
                    *(float2*)&C[(size_t)r * FEAT + c] = o;
                } else {
                    const int h = c >> 6, d = c & 63;
                    *(float2*)&C[(((size_t)(bb2 * HEADS + h)) * LSEQ + l) * DIM + d] = o;
                }
            }
        }
    }
}

// ---------------------------------------------------------------------------
// Fused attention, warp-strip layout, k-halves for register pressure.
// Block = (128 q, h, b); warp w owns q rows [w*16, w*16+16), full 128 k.
// Q frags in regs; S computed 64 k-cols at a time; P->PV via warp shuffles.
// smem floats: tp[4096] | Ks[128][68] | Vt[64][131]
// ---------------------------------------------------------------------------
#define KS_OFF 4096
#define VT_OFF (KS_OFF + 128 * 68)
#define ATT_SMEM ((VT_OFF + 64 * 131) * 4)   // 84736 B

__global__ __launch_bounds__(256, 2) void attn_tf32(const float* __restrict__ tpar,
                                                    float* __restrict__ outp)
{
    extern __shared__ float sma[];
    float* tp = sma;
    uint32_t* Ks = (uint32_t*)(sma + KS_OFF);
    uint32_t* Vt = (uint32_t*)(sma + VT_OFF);

    const int tid = threadIdx.x;
    const int wid = tid >> 5, lane = tid & 31;
    const int g = lane >> 2, tq = lane & 3;
    const int q0 = blockIdx.x * 128;
    const int h = blockIdx.y;
    const int b = blockIdx.z;

    const float* qp = g_q + ((size_t)(b * HEADS + h)) * LSEQ * DIM;
    const float* kp = g_k + ((size_t)(b * HEADS + h)) * LSEQ * DIM;
    const float* vp = g_v + ((size_t)(b * HEADS + h)) * LSEQ * DIM;

    for (int i = tid; i < 4096; i += 256) tp[i] = tpar[h * 4096 + i];

    // ---- stage Q into Ks, extract frags to registers ----
#pragma unroll
    for (int i = 0; i < 8; i++) {
        const int idx = i * 256 + tid;
        const int r = idx >> 4, c4 = (idx & 15) << 2;
        const int qg = q0 + r;
        uint4 v = (qg < LSEQ) ? *(const uint4*)&qp[(size_t)qg * DIM + c4]
                              : make_uint4(0u, 0u, 0u, 0u);
        *(uint4*)&Ks[r * 68 + c4] = v;
    }
    __syncthreads();

    const int rowlo = wid * 16 + g;
    uint32_t qf[8][4];
#pragma unroll
    for (int ks = 0; ks < 8; ks++) {
        const int base = rowlo * 68 + ks * 8 + tq;
        qf[ks][0] = Ks[base];
        qf[ks][1] = Ks[base + 8 * 68];
        qf[ks][2] = Ks[base + 4];
        qf[ks][3] = Ks[base + 8 * 68 + 4];
    }

    const int qg_lo = q0 + rowlo, qg_hi = qg_lo + 8;
    const bool vq_lo = qg_lo < LSEQ, vq_hi = qg_hi < LSEQ;
    const int qi_lo = (qg_lo - 1) >> 5, qj_lo = (qg_lo - 1) & 31;
    const int qi_hi = (qg_hi - 1) >> 5, qj_hi = (qg_hi - 1) & 31;

    float acc_o[8][4];
#pragma unroll
    for (int j = 0; j < 8; j++)
#pragma unroll
        for (int q = 0; q < 4; q++) acc_o[j][q] = 0.f;
    float rs0 = 0.f, rs1 = 0.f;

    const uint32_t ks_base = smem_u32(Ks);

#pragma unroll 1
    for (int kt = 0; kt < 9; kt++) {
        const int ktb = kt * 128;
        __syncthreads();   // Ks/Vt reuse guard (first iter: qf extraction done)

        // ---- K via cp.async: full 128 rows x 64 floats (zfill OOB) ----
#pragma unroll
        for (int i = 0; i < 8; i++) {
            const int idx = i * 256 + tid;
            const int r = idx >> 4, c4 = (idx & 15) << 2;   // row, 4-float chunk
            const int kg = ktb + r;
            cp16(ks_base + (uint32_t)(r * 68 + c4) * 4,
                 kp + (size_t)kg * DIM + c4, kg < LSEQ);
        }
        CP_COMMIT();

        // ---- V scalar -> Vt transposed ----
#pragma unroll
        for (int i = 0; i < 8; i++) {
            const int idx = i * 256 + tid;
            const int r = idx >> 4, c4 = (idx & 15) << 2;
            const int kg = ktb + r;
            uint4 vv = (kg < LSEQ) ? *(const uint4*)&vp[(size_t)kg * DIM + c4]
                                   : make_uint4(0u, 0u, 0u, 0u);
            Vt[(c4 + 0) * 131 + r] = vv.x;
            Vt[(c4 + 1) * 131 + r] = vv.y;
            Vt[(c4 + 2) * 131 + r] = vv.z;
            Vt[(c4 + 3) * 131 + r] = vv.w;
        }
        CP_WAIT0();
        __syncthreads();

        // ---- two 64-col halves: S -> mask -> P -> PV ----
#pragma unroll
        for (int hk = 0; hk < 2; hk++) {
            const int kb = hk * 64;

            float s_acc[8][4];
#pragma unroll
            for (int j = 0; j < 8; j++)
#pragma unroll
                for (int q = 0; q < 4; q++) s_acc[j][q] = 0.f;
#pragma unroll
            for (int ks = 0; ks < 8; ks++) {
                const int kd = ks * 8;
#pragma unroll
                for (int nf = 0; nf < 8; nf++) {
                    const int bb = (kb + nf * 8 + g) * 68 + kd + tq;
                    mma_tf32(s_acc[nf], qf[ks], Ks[bb], Ks[bb + 4]);
                }
            }

            // mask + eps + rowsum -> P (tf32 bits)
            uint32_t p[8][4];
#pragma unroll
            for (int nf = 0; nf < 8; nf++) {
                const int kl0 = kb + nf * 8 + 2 * tq;
#pragma unroll
                for (int e = 0; e < 2; e++) {
                    const int kg = ktb + kl0 + e;
                    const bool kvld = kg < LSEQ;
                    const int kk = kg - 1;
                    const int kki = kk >> 5, kkj = kk & 31;
                    float vlo = 0.f;
                    if (vq_lo && kvld) {
                        float tm = 1.f;
                        if (qg_lo != 0 && kg != 0)
                            tm = fabsf(tp[(qi_lo - kki + 32) * 64 + (qj_lo - kkj + 32)]);
                        vlo = fmaf(s_acc[nf][e], tm, EPSF);
                    }
                    float vhi = 0.f;
                    if (vq_hi && kvld) {
                        float tm = 1.f;
                        if (kg != 0)   // qg_hi >= 8, never CLS
                            tm = fabsf(tp[(qi_hi - kki + 32) * 64 + (qj_hi - kkj + 32)]);
                        vhi = fmaf(s_acc[nf][2 + e], tm, EPSF);
                    }
                    rs0 += vlo;
                    rs1 += vhi;
                    p[nf][e] = tf32u(vlo);
                    p[nf][2 + e] = tf32u(vhi);
                }
            }

            // PV for this half: shuffle P into A-fragments
            const int lbase = lane & 28;
            const int slo = lbase | (tq >> 1);
            const int shi = slo + 2;
            const bool odd = (tq & 1);
#pragma unroll
            for (int s = 0; s < 8; s++) {
                uint32_t a[4];
                uint32_t e0 = __shfl_sync(0xffffffffu, p[s][0], slo);
                uint32_t e1 = __shfl_sync(0xffffffffu, p[s][1], slo);
                a[0] = odd ? e1 : e0;
                e0 = __shfl_sync(0xffffffffu, p[s][0], shi);
                e1 = __shfl_sync(0xffffffffu, p[s][1], shi);
                a[2] = odd ? e1 : e0;
                e0 = __shfl_sync(0xffffffffu, p[s][2], slo);
                e1 = __shfl_sync(0xffffffffu, p[s][3], slo);
                a[1] = odd ? e1 : e0;
                e0 = __shfl_sync(0xffffffffu, p[s][2], shi);
                e1 = __shfl_sync(0xffffffffu, p[s][3], shi);
                a[3] = odd ? e1 : e0;
#pragma unroll
                for (int nf = 0; nf < 8; nf++) {
                    const int bb = (nf * 8 + g) * 131 + kb + s * 8 + tq;
                    mma_tf32(acc_o[nf], a, Vt[bb], Vt[bb + 4]);
                }
            }
        }
    }

    // ---- rowsum reduce within quads (rows are warp-exclusive) ----
    rs0 += __shfl_xor_sync(0xffffffffu, rs0, 1);
    rs0 += __shfl_xor_sync(0xffffffffu, rs0, 2);
    rs1 += __shfl_xor_sync(0xffffffffu, rs1, 1);
    rs1 += __shfl_xor_sync(0xffffffffu, rs1, 2);

    // ---- normalize + write (tf32-rounded for the pre-rounded WO GEMM) ----
    if (vq_lo) {
        const float inv = 1.f / rs0;
        float* dst = outp + (size_t)(b * LSEQ + qg_lo) * FEAT + h * 64;
#pragma unroll
        for (int nf = 0; nf < 8; nf++) {
            const int d0 = nf * 8 + 2 * tq;
            *(float2*)&dst[d0] = make_float2(tf32f(acc_o[nf][0] * inv),
                                             tf32f(acc_o[nf][1] * inv));
        }
    }
    if (vq_hi) {
        const float inv = 1.f / rs1;
        float* dst = outp + (size_t)(b * LSEQ + qg_hi) * FEAT + h * 64;
#pragma unroll
        for (int nf = 0; nf < 8; nf++) {
            const int d0 = nf * 8 + 2 * tq;
            *(float2*)&dst[d0] = make_float2(tf32f(acc_o[nf][2] * inv),
                                             tf32f(acc_o[nf][3] * inv));
        }
    }
}

// ---------------------------------------------------------------------------
extern "C" void kernel_launch(void* const* d_in, const int* in_sizes, int n_in,
                              void* d_out, int out_size)
{
    const float* x    = (const float*)d_in[0];
    const float* wq   = (const float*)d_in[1];
    const float* bq   = (const float*)d_in[2];
    const float* wk   = (const float*)d_in[3];
    const float* bk   = (const float*)d_in[4];
    const float* wv   = (const float*)d_in[5];
    const float* bv   = (const float*)d_in[6];
    const float* wo   = (const float*)d_in[7];
    const float* bo   = (const float*)d_in[8];
    const float* tpar = (const float*)d_in[9];
    float* out = (float*)d_out;

    float *qp, *kp, *vp, *op, *xp, *wtp;
    cudaGetSymbolAddress((void**)&qp, g_q);
    cudaGetSymbolAddress((void**)&kp, g_k);
    cudaGetSymbolAddress((void**)&vp, g_v);
    cudaGetSymbolAddress((void**)&op, g_o);
    cudaGetSymbolAddress((void**)&xp, g_x);
    cudaGetSymbolAddress((void**)&wtp, g_wt);

    // prepasses: round X to tf32; transpose+round all weights
    xconv<<<(MROWS * FEAT) / (4 * 256), 256>>>(x, xp);
    dim3 wg(FEAT / 32, FEAT / 32), wb(32, 8);
    wtrans<<<wg, wb>>>(wq, wtp + 0 * (size_t)FEAT * FEAT);
    wtrans<<<wg, wb>>>(wk, wtp + 1 * (size_t)FEAT * FEAT);
    wtrans<<<wg, wb>>>(wv, wtp + 2 * (size_t)FEAT * FEAT);
    wtrans<<<wg, wb>>>(wo, wtp + 3 * (size_t)FEAT * FEAT);

    cudaFuncSetAttribute(tgemm<0>, cudaFuncAttributeMaxDynamicSharedMemorySize, TG_SMEM);
    cudaFuncSetAttribute(tgemm<1>, cudaFuncAttributeMaxDynamicSharedMemorySize, TG_SMEM);
    cudaFuncSetAttribute(tgemm<2>, cudaFuncAttributeMaxDynamicSharedMemorySize, TG_SMEM);
    cudaFuncSetAttribute(tgemm<3>, cudaFuncAttributeMaxDynamicSharedMemorySize, TG_SMEM);

    dim3 tg((MROWS + 127) / 128, FEAT / 128);   // 129 x 6
    tgemm<0><<<tg, 256, TG_SMEM>>>(xp, wtp + 0 * (size_t)FEAT * FEAT, bq, qp);
    tgemm<1><<<tg, 256, TG_SMEM>>>(xp, wtp + 1 * (size_t)FEAT * FEAT, bk, kp);
    tgemm<2><<<tg, 256, TG_SMEM>>>(xp, wtp + 2 * (size_t)FEAT * FEAT, bv, vp);

    cudaFuncSetAttribute(attn_tf32, cudaFuncAttributeMaxDynamicSharedMemorySize,
                         ATT_SMEM);
    attn_tf32<<<dim3(9, HEADS, BATCH), 256, ATT_SMEM>>>(tpar, op);

    tgemm<3><<<tg, 256, TG_SMEM>>>(op, wtp + 3 * (size_t)FEAT * FEAT, bo, out);
}

// round 16
// speedup vs baseline: 2.9301x; 1.1956x over previous
#include <cuda_runtime.h>
#include <cstdint>

#define BATCH 16
#define HEADS 12
#define DIM 64
#define FEAT 768
#define LSEQ 1025
#define MROWS (BATCH * LSEQ)   // 16400
#define EPSF 1e-8f

// Scratch (allocation-free rule: __device__ globals)
__device__ float g_q[(size_t)BATCH * HEADS * LSEQ * DIM];
__device__ float g_k[(size_t)BATCH * HEADS * LSEQ * DIM];
__device__ float g_v[(size_t)BATCH * HEADS * LSEQ * DIM];
__device__ float g_o[(size_t)MROWS * FEAT];
__device__ float g_x[(size_t)MROWS * FEAT];          // tf32-rounded X
__device__ float g_wt[4][(size_t)FEAT * FEAT];       // tf32-rounded W^T [n][k]; 0..2 = qkv packed

// ---------------------------------------------------------------------------
// helpers
// ---------------------------------------------------------------------------
__device__ __forceinline__ uint32_t smem_u32(const void* p) {
    uint32_t a;
    asm("{ .reg .u64 t; cvta.to.shared.u64 t, %1; cvt.u32.u64 %0, t; }"
        : "=r"(a) : "l"(p));
    return a;
}
__device__ __forceinline__ uint32_t tf32u(float f) {
    uint32_t u;
    asm("cvt.rna.tf32.f32 %0, %1;" : "=r"(u) : "f"(f));
    return u;
}
__device__ __forceinline__ float tf32f(float f) {
    return __uint_as_float(tf32u(f));
}
__device__ __forceinline__ void mma_tf32(float* d, const uint32_t* a,
                                         uint32_t b0, uint32_t b1) {
    asm volatile("mma.sync.aligned.m16n8k8.row.col.f32.tf32.tf32.f32 "
                 "{%0,%1,%2,%3}, {%4,%5,%6,%7}, {%8,%9}, {%0,%1,%2,%3};"
                 : "+f"(d[0]), "+f"(d[1]), "+f"(d[2]), "+f"(d[3])
                 : "r"(a[0]), "r"(a[1]), "r"(a[2]), "r"(a[3]),
                   "r"(b0), "r"(b1));
}
__device__ __forceinline__ void cp16(uint32_t dst, const void* src, bool v) {
    int sz = v ? 16 : 0;
    asm volatile("cp.async.cg.shared.global [%0], [%1], 16, %2;"
                 :: "r"(dst), "l"(src), "r"(sz) : "memory");
}
#define CP_COMMIT() asm volatile("cp.async.commit_group;" ::: "memory")
#define CP_WAIT1()  asm volatile("cp.async.wait_group 1;" ::: "memory")
#define CP_WAIT0()  asm volatile("cp.async.wait_group 0;" ::: "memory")

// ---------------------------------------------------------------------------
// prepasses
// ---------------------------------------------------------------------------
__global__ void xconv(const float* __restrict__ X, float* __restrict__ XO) {
    const int i = blockIdx.x * 256 + threadIdx.x;   // float4 index
    float4 v = ((const float4*)X)[i];
    float4 o = make_float4(tf32f(v.x), tf32f(v.y), tf32f(v.z), tf32f(v.w));
    ((float4*)XO)[i] = o;
}
// W[k][n] (768x768 row-major) -> WT[n][k] tf32-rounded
__global__ void wtrans(const float* __restrict__ W, float* __restrict__ WT) {
    __shared__ float t[32][33];
    const int k0 = blockIdx.x * 32, n0 = blockIdx.y * 32;
    const int x = threadIdx.x, y = threadIdx.y;    // 32 x 8
#pragma unroll
    for (int i = y; i < 32; i += 8)
        t[i][x] = W[(size_t)(k0 + i) * FEAT + n0 + x];
    __syncthreads();
#pragma unroll
    for (int i = y; i < 32; i += 8)
        WT[(size_t)(n0 + i) * FEAT + k0 + x] = tf32f(t[x][i]);
}

// ---------------------------------------------------------------------------
// Pipelined tf32 GEMM core (CTA 128x128, BK=32, cp.async double-buffered).
// ---------------------------------------------------------------------------
#define TG_BUF 9216               // floats per buffer (A 4608 + B 4608)
#define TG_SMEM (2 * TG_BUF * 4)  // 73728 bytes

// Fused QKV: C = X * [WqT;WkT;WvT]^T, N = 2304. Epilogue per matrix.
__global__ __launch_bounds__(256, 2) void tgemm_qkv(
    const float* __restrict__ A, const float* __restrict__ WT,
    const float* __restrict__ bq, const float* __restrict__ bk,
    const float* __restrict__ bv,
    float* __restrict__ Q, float* __restrict__ K, float* __restrict__ V)
{
    extern __shared__ uint32_t smg[];
    const int tid = threadIdx.x;
    const int wid = tid >> 5, lane = tid & 31;
    const int g = lane >> 2, tq = lane & 3;
    const int m0 = blockIdx.x * 128, n0 = blockIdx.y * 128;
    const int mw = (wid >> 1) * 32, nw = (wid & 1) * 64;

    const int mat = n0 / FEAT;                  // 0=q,1=k,2=v (CTA-uniform)
    const float* bias = (mat == 0) ? bq : (mat == 1) ? bk : bv;
    float* C = (mat == 0) ? Q : (mat == 1) ? K : V;
    const int nbase = n0 - mat * FEAT;

    const uint32_t sbase = smem_u32(smg);
    const int ar = tid >> 1, half = (tid & 1) * 16;
    const bool aval = (m0 + ar) < MROWS;
    const float* asrc = A + (size_t)(m0 + ar) * FEAT + half;
    const float* bsrc = WT + (size_t)(n0 + ar) * FEAT + half;
    const uint32_t soffA = (uint32_t)(ar * 36 + half) * 4;
    const uint32_t soffB = soffA + 4608u * 4;

    float acc[2][8][4];
#pragma unroll
    for (int i = 0; i < 2; i++)
#pragma unroll
        for (int j = 0; j < 8; j++)
#pragma unroll
            for (int q = 0; q < 4; q++) acc[i][j][q] = 0.f;

    {
#pragma unroll
        for (int j = 0; j < 4; j++) {
            cp16(sbase + soffA + 16u * j, asrc + 4 * j, aval);
            cp16(sbase + soffB + 16u * j, bsrc + 4 * j, true);
        }
        CP_COMMIT();
    }

#pragma unroll 1
    for (int s = 0; s < 24; s++) {
        const uint32_t bufo = (uint32_t)(s & 1) * TG_BUF;
        if (s + 1 < 24) {
            const uint32_t nbo = (uint32_t)((s + 1) & 1) * TG_BUF * 4;
            const int k0 = (s + 1) * 32;
#pragma unroll
            for (int j = 0; j < 4; j++) {
                cp16(sbase + nbo + soffA + 16u * j, asrc + k0 + 4 * j, aval);
                cp16(sbase + nbo + soffB + 16u * j, bsrc + k0 + 4 * j, true);
            }
            CP_COMMIT();
            CP_WAIT1();
        } else {
            CP_WAIT0();
        }
        __syncthreads();

        const uint32_t* smA = smg + bufo;
        const uint32_t* smB = smg + bufo + 4608;
#pragma unroll
        for (int ks = 0; ks < 4; ks++) {
            const int kd = ks * 8;
            uint32_t a[2][4];
#pragma unroll
            for (int mf = 0; mf < 2; mf++) {
                const int base = (mw + mf * 16 + g) * 36 + kd + tq;
                a[mf][0] = smA[base];
                a[mf][1] = smA[base + 8 * 36];
                a[mf][2] = smA[base + 4];
                a[mf][3] = smA[base + 8 * 36 + 4];
            }
#pragma unroll
            for (int nf = 0; nf < 8; nf++) {
                const int bb = (nw + nf * 8 + g) * 36 + kd + tq;
                const uint32_t b0 = smB[bb], b1 = smB[bb + 4];
                mma_tf32(acc[0][nf], a[0], b0, b1);
                mma_tf32(acc[1][nf], a[1], b0, b1);
            }
        }
        __syncthreads();
    }

#pragma unroll
    for (int mf = 0; mf < 2; mf++) {
#pragma unroll
        for (int hf = 0; hf < 2; hf++) {
            const int r = m0 + mw + mf * 16 + g + hf * 8;
            if (r >= MROWS) continue;
            const int bb2 = r / LSEQ, l = r - bb2 * LSEQ;
#pragma unroll
            for (int nf = 0; nf < 8; nf++) {
                const int c = nbase + nw + nf * 8 + tq * 2;
                float v0 = acc[mf][nf][hf * 2 + 0] + bias[c];
                float v1 = acc[mf][nf][hf * 2 + 1] + bias[c + 1];
                if (mat == 0) {
                    v0 = tf32f(fmaxf(v0 * 0.125f, 0.f) + EPSF);
                    v1 = tf32f(fmaxf(v1 * 0.125f, 0.f) + EPSF);
                } else if (mat == 1) {
                    v0 = tf32f(fmaxf(v0, 0.f) + EPSF);
                    v1 = tf32f(fmaxf(v1, 0.f) + EPSF);
                } else {
                    v0 = tf32f(v0);
                    v1 = tf32f(v1);
                }
                const int h = c >> 6, d = c & 63;
                *(float2*)&C[(((size_t)(bb2 * HEADS + h)) * LSEQ + l) * DIM + d] =
                    make_float2(v0, v1);
            }
        }
    }
}

// Output GEMM: out = O * WoT^T + bo, row-major [M,768].
__global__ __launch_bounds__(256, 2) void tgemm_out(
    const float* __restrict__ A, const float* __restrict__ WT,
    const float* __restrict__ bias, float* __restrict__ C)
{
    extern __shared__ uint32_t smg[];
    const int tid = threadIdx.x;
    const int wid = tid >> 5, lane = tid & 31;
    const int g = lane >> 2, tq = lane & 3;
    const int m0 = blockIdx.x * 128, n0 = blockIdx.y * 128;
    const int mw = (wid >> 1) * 32, nw = (wid & 1) * 64;

    const uint32_t sbase = smem_u32(smg);
    const int ar = tid >> 1, half = (tid & 1) * 16;
    const bool aval = (m0 + ar) < MROWS;
    const float* asrc = A + (size_t)(m0 + ar) * FEAT + half;
    const float* bsrc = WT + (size_t)(n0 + ar) * FEAT + half;
    const uint32_t soffA = (uint32_t)(ar * 36 + half) * 4;
    const uint32_t soffB = soffA + 4608u * 4;

    float acc[2][8][4];
#pragma unroll
    for (int i = 0; i < 2; i++)
#pragma unroll
        for (int j = 0; j < 8; j++)
#pragma unroll
            for (int q = 0; q < 4; q++) acc[i][j][q] = 0.f;

    {
#pragma unroll
        for (int j = 0; j < 4; j++) {
            cp16(sbase + soffA + 16u * j, asrc + 4 * j, aval);
            cp16(sbase + soffB + 16u * j, bsrc + 4 * j, true);
        }
        CP_COMMIT();
    }

#pragma unroll 1
    for (int s = 0; s < 24; s++) {
        const uint32_t bufo = (uint32_t)(s & 1) * TG_BUF;
        if (s + 1 < 24) {
            const uint32_t nbo = (uint32_t)((s + 1) & 1) * TG_BUF * 4;
            const int k0 = (s + 1) * 32;
#pragma unroll
            for (int j = 0; j < 4; j++) {
                cp16(sbase + nbo + soffA + 16u * j, asrc + k0 + 4 * j, aval);
                cp16(sbase + nbo + soffB + 16u * j, bsrc + k0 + 4 * j, true);
            }
            CP_COMMIT();
            CP_WAIT1();
        } else {
            CP_WAIT0();
        }
        __syncthreads();

        const uint32_t* smA = smg + bufo;
        const uint32_t* smB = smg + bufo + 4608;
#pragma unroll
        for (int ks = 0; ks < 4; ks++) {
            const int kd = ks * 8;
            uint32_t a[2][4];
#pragma unroll
            for (int mf = 0; mf < 2; mf++) {
                const int base = (mw + mf * 16 + g) * 36 + kd + tq;
                a[mf][0] = smA[base];
                a[mf][1] = smA[base + 8 * 36];
                a[mf][2] = smA[base + 4];
                a[mf][3] = smA[base + 8 * 36 + 4];
            }
#pragma unroll
            for (int nf = 0; nf < 8; nf++) {
                const int bb = (nw + nf * 8 + g) * 36 + kd + tq;
                const uint32_t b0 = smB[bb], b1 = smB[bb + 4];
                mma_tf32(acc[0][nf], a[0], b0, b1);
                mma_tf32(acc[1][nf], a[1], b0, b1);
            }
        }
        __syncthreads();
    }

#pragma unroll
    for (int mf = 0; mf < 2; mf++) {
#pragma unroll
        for (int hf = 0; hf < 2; hf++) {
            const int r = m0 + mw + mf * 16 + g + hf * 8;
            if (r >= MROWS) continue;
#pragma unroll
            for (int nf = 0; nf < 8; nf++) {
                const int c = n0 + nw + nf * 8 + tq * 2;
                float v0 = acc[mf][nf][hf * 2 + 0] + bias[c];
                float v1 = acc[mf][nf][hf * 2 + 1] + bias[c + 1];
                *(float2*)&C[(size_t)r * FEAT + c] = make_float2(v0, v1);
            }
        }
    }
}

// ---------------------------------------------------------------------------
// Fused attention for q in [1,1024], k in [1,1024]: exactly 8x8 full tiles,
// no bounds checks, unconditional Toeplitz mask. CLS column (k=0) added as
// scalar epilogue per row. CLS row (q=0) handled by cls_row kernel.
// smem floats: tp[4096] | Ks[128][68] | Vt[64][131]
// ---------------------------------------------------------------------------
#define KS_OFF 4096
#define VT_OFF (KS_OFF + 128 * 68)
#define ATT_SMEM ((VT_OFF + 64 * 131) * 4)   // 84736 B

__global__ __launch_bounds__(256, 2) void attn_tf32(const float* __restrict__ tpar,
                                                    float* __restrict__ outp)
{
    extern __shared__ float sma[];
    float* tp = sma;
    uint32_t* Ks = (uint32_t*)(sma + KS_OFF);
    uint32_t* Vt = (uint32_t*)(sma + VT_OFF);

    const int tid = threadIdx.x;
    const int wid = tid >> 5, lane = tid & 31;
    const int g = lane >> 2, tq = lane & 3;
    const int q0 = 1 + blockIdx.x * 128;      // q rows [q0, q0+127], all valid
    const int h = blockIdx.y;
    const int b = blockIdx.z;

    const float* qp = g_q + ((size_t)(b * HEADS + h)) * LSEQ * DIM;
    const float* kp = g_k + ((size_t)(b * HEADS + h)) * LSEQ * DIM;
    const float* vp = g_v + ((size_t)(b * HEADS + h)) * LSEQ * DIM;

    for (int i = tid; i < 4096; i += 256) tp[i] = tpar[h * 4096 + i];

    // ---- stage Q into Ks, extract frags to registers ----
#pragma unroll
    for (int i = 0; i < 8; i++) {
        const int idx = i * 256 + tid;
        const int r = idx >> 4, c4 = (idx & 15) << 2;
        *(uint4*)&Ks[r * 68 + c4] = *(const uint4*)&qp[(size_t)(q0 + r) * DIM + c4];
    }
    __syncthreads();

    const int rowlo = wid * 16 + g;
    uint32_t qf[8][4];
#pragma unroll
    for (int ks = 0; ks < 8; ks++) {
        const int base = rowlo * 68 + ks * 8 + tq;
        qf[ks][0] = Ks[base];
        qf[ks][1] = Ks[base + 8 * 68];
        qf[ks][2] = Ks[base + 4];
        qf[ks][3] = Ks[base + 8 * 68 + 4];
    }

    const int qg_lo = q0 + rowlo, qg_hi = qg_lo + 8;
    const int qq_lo = qg_lo - 1, qq_hi = qg_hi - 1;       // patch index 0..1023
    const int qi_lo = qq_lo >> 5, qj_lo = qq_lo & 31;
    const int qi_hi = qq_hi >> 5, qj_hi = qq_hi & 31;

    float acc_o[8][4];
#pragma unroll
    for (int j = 0; j < 8; j++)
#pragma unroll
        for (int q = 0; q < 4; q++) acc_o[j][q] = 0.f;
    float rs0 = 0.f, rs1 = 0.f;

    const uint32_t ks_base = smem_u32(Ks);

#pragma unroll 1
    for (int kt = 0; kt < 8; kt++) {
        const int ktb = kt * 128;                  // patch index base (k row = 1+ktb+r)
        __syncthreads();   // Ks/Vt reuse guard (first iter: qf extraction done)

        // ---- K via cp.async: 128 rows x 64 floats, all valid ----
#pragma unroll
        for (int i = 0; i < 8; i++) {
            const int idx = i * 256 + tid;
            const int r = idx >> 4, c4 = (idx & 15) << 2;
            cp16(ks_base + (uint32_t)(r * 68 + c4) * 4,
                 kp + (size_t)(1 + ktb + r) * DIM + c4, true);
        }
        CP_COMMIT();

        // ---- V scalar -> Vt transposed ----
#pragma unroll
        for (int i = 0; i < 8; i++) {
            const int idx = i * 256 + tid;
            const int r = idx >> 4, c4 = (idx & 15) << 2;
            uint4 vv = *(const uint4*)&vp[(size_t)(1 + ktb + r) * DIM + c4];
            Vt[(c4 + 0) * 131 + r] = vv.x;
            Vt[(c4 + 1) * 131 + r] = vv.y;
            Vt[(c4 + 2) * 131 + r] = vv.z;
            Vt[(c4 + 3) * 131 + r] = vv.w;
        }
        CP_WAIT0();
        __syncthreads();

        // ---- two 64-col halves: S -> mask -> P -> PV ----
#pragma unroll
        for (int hk = 0; hk < 2; hk++) {
            const int kb = hk * 64;

            float s_acc[8][4];
#pragma unroll
            for (int j = 0; j < 8; j++)
#pragma unroll
                for (int q = 0; q < 4; q++) s_acc[j][q] = 0.f;
#pragma unroll
            for (int ks = 0; ks < 8; ks++) {
                const int kd = ks * 8;
#pragma unroll
                for (int nf = 0; nf < 8; nf++) {
                    const int bb = (kb + nf * 8 + g) * 68 + kd + tq;
                    mma_tf32(s_acc[nf], qf[ks], Ks[bb], Ks[bb + 4]);
                }
            }

            // unconditional mask + eps + rowsum -> P (tf32 bits)
            uint32_t p[8][4];
#pragma unroll
            for (int nf = 0; nf < 8; nf++) {
                const int kl0 = kb + nf * 8 + 2 * tq;
#pragma unroll
                for (int e = 0; e < 2; e++) {
                    const int kk = ktb + kl0 + e;      // patch index 0..1023
                    const int kki = kk >> 5, kkj = kk & 31;
                    const float tlo = fabsf(tp[(qi_lo - kki + 32) * 64 + (qj_lo - kkj + 32)]);
                    const float thi = fabsf(tp[(qi_hi - kki + 32) * 64 + (qj_hi - kkj + 32)]);
                    const float vlo = fmaf(s_acc[nf][e], tlo, EPSF);
                    const float vhi = fmaf(s_acc[nf][2 + e], thi, EPSF);
                    rs0 += vlo;
                    rs1 += vhi;
                    p[nf][e] = tf32u(vlo);
                    p[nf][2 + e] = tf32u(vhi);
                }
            }

            // PV for this half: shuffle P into A-fragments
            const int lbase = lane & 28;
            const int slo = lbase | (tq >> 1);
            const int shi = slo + 2;
            const bool odd = (tq & 1);
#pragma unroll
            for (int s = 0; s < 8; s++) {
                uint32_t a[4];
                uint32_t e0 = __shfl_sync(0xffffffffu, p[s][0], slo);
                uint32_t e1 = __shfl_sync(0xffffffffu, p[s][1], slo);
                a[0] = odd ? e1 : e0;
                e0 = __shfl_sync(0xffffffffu, p[s][0], shi);
                e1 = __shfl_sync(0xffffffffu, p[s][1], shi);
                a[2] = odd ? e1 : e0;
                e0 = __shfl_sync(0xffffffffu, p[s][2], slo);
                e1 = __shfl_sync(0xffffffffu, p[s][3], slo);
                a[1] = odd ? e1 : e0;
                e0 = __shfl_sync(0xffffffffu, p[s][2], shi);
                e1 = __shfl_sync(0xffffffffu, p[s][3], shi);
                a[3] = odd ? e1 : e0;
#pragma unroll
                for (int nf = 0; nf < 8; nf++) {
                    const int bb = (nf * 8 + g) * 131 + kb + s * 8 + tq;
                    mma_tf32(acc_o[nf], a, Vt[bb], Vt[bb + 4]);
                }
            }
        }
    }

    // ---- rowsum reduce within quads ----
    rs0 += __shfl_xor_sync(0xffffffffu, rs0, 1);
    rs0 += __shfl_xor_sync(0xffffffffu, rs0, 2);
    rs1 += __shfl_xor_sync(0xffffffffu, rs1, 1);
    rs1 += __shfl_xor_sync(0xffffffffu, rs1, 2);

    // ---- CLS column (k=0, tm=1): scalar dot + rank-1 update ----
    {
        float d_lo = 0.f, d_hi = 0.f;
        const float* qlo = qp + (size_t)qg_lo * DIM + tq * 16;
        const float* qhi = qp + (size_t)qg_hi * DIM + tq * 16;
        const float* k0 = kp + tq * 16;
#pragma unroll
        for (int i = 0; i < 4; i++) {
            float4 kv = *(const float4*)&k0[i * 4];
            float4 ql = *(const float4*)&qlo[i * 4];
            float4 qh = *(const float4*)&qhi[i * 4];
            d_lo += ql.x * kv.x + ql.y * kv.y + ql.z * kv.z + ql.w * kv.w;
            d_hi += qh.x * kv.x + qh.y * kv.y + qh.z * kv.z + qh.w * kv.w;
        }
        d_lo += __shfl_xor_sync(0xffffffffu, d_lo, 1);
        d_lo += __shfl_xor_sync(0xffffffffu, d_lo, 2);
        d_hi += __shfl_xor_sync(0xffffffffu, d_hi, 1);
        d_hi += __shfl_xor_sync(0xffffffffu, d_hi, 2);
        const float p0_lo = d_lo + EPSF, p0_hi = d_hi + EPSF;
        rs0 += p0_lo;
        rs1 += p0_hi;
#pragma unroll
        for (int nf = 0; nf < 8; nf++) {
            const int d0 = nf * 8 + 2 * tq;
            float2 v0 = *(const float2*)&vp[d0];
            acc_o[nf][0] += p0_lo * v0.x;
            acc_o[nf][1] += p0_lo * v0.y;
            acc_o[nf][2] += p0_hi * v0.x;
            acc_o[nf][3] += p0_hi * v0.y;
        }
    }

    // ---- normalize + write (tf32-rounded for the pre-rounded WO GEMM) ----
    {
        const float inv = 1.f / rs0;
        float* dst = outp + (size_t)(b * LSEQ + qg_lo) * FEAT + h * 64;
#pragma unroll
        for (int nf = 0; nf < 8; nf++) {
            const int d0 = nf * 8 + 2 * tq;
            *(float2*)&dst[d0] = make_float2(tf32f(acc_o[nf][0] * inv),
                                             tf32f(acc_o[nf][1] * inv));
        }
    }
    {
        const float inv = 1.f / rs1;
        float* dst = outp + (size_t)(b * LSEQ + qg_hi) * FEAT + h * 64;
#pragma unroll
        for (int nf = 0; nf < 8; nf++) {
            const int d0 = nf * 8 + 2 * tq;
            *(float2*)&dst[d0] = make_float2(tf32f(acc_o[nf][2] * inv),
                                             tf32f(acc_o[nf][3] * inv));
        }
    }
}

// ---------------------------------------------------------------------------
// CLS row (q=0): tm = 1 everywhere (padded row). Grid (BATCH, HEADS), 256 thr.
// ---------------------------------------------------------------------------
__global__ __launch_bounds__(256) void cls_row(float* __restrict__ outp)
{
    __shared__ float q0s[64];
    __shared__ float ps[LSEQ];
    __shared__ float red[256];

    const int b = blockIdx.x, h = blockIdx.y;
    const int tid = threadIdx.x;
    const float* qp = g_q + ((size_t)(b * HEADS + h)) * LSEQ * DIM;
    const float* kp = g_k + ((size_t)(b * HEADS + h)) * LSEQ * DIM;
    const float* vp = g_v + ((size_t)(b * HEADS + h)) * LSEQ * DIM;

    if (tid < 64) q0s[tid] = qp[tid];
    __syncthreads();

    float lsum = 0.f;
    for (int k = tid; k < LSEQ; k += 256) {
        const float4* kr = (const float4*)&kp[(size_t)k * DIM];
        float dot = 0.f;
#pragma unroll
        for (int i = 0; i < 16; i++) {
            float4 kv = kr[i];
            const float* qq = &q0s[i * 4];
            dot += qq[0] * kv.x + qq[1] * kv.y + qq[2] * kv.z + qq[3] * kv.w;
        }
        const float p = dot + EPSF;
        ps[k] = p;
        lsum += p;
    }
    red[tid] = lsum;
    __syncthreads();
    for (int s = 128; s > 0; s >>= 1) {
        if (tid < s) red[tid] += red[tid + s];
        __syncthreads();
    }
    const float inv = 1.f / red[0];
    __syncthreads();

    const int d = tid & 63, ch = tid >> 6;
    float acc = 0.f;
    for (int k = ch; k < LSEQ; k += 4)
        acc += ps[k] * vp[(size_t)k * DIM + d];
    red[tid] = acc;
    __syncthreads();
    if (tid < 64) {
        const float o = (red[tid] + red[64 + tid] + red[128 + tid] + red[192 + tid]) * inv;
        outp[(size_t)(b * LSEQ) * FEAT + h * 64 + tid] = tf32f(o);
    }
}

// ---------------------------------------------------------------------------
extern "C" void kernel_launch(void* const* d_in, const int* in_sizes, int n_in,
                              void* d_out, int out_size)
{
    const float* x    = (const float*)d_in[0];
    const float* wq   = (const float*)d_in[1];
    const float* bq   = (const float*)d_in[2];
    const float* wk   = (const float*)d_in[3];
    const float* bk   = (const float*)d_in[4];
    const float* wv   = (const float*)d_in[5];
    const float* bv   = (const float*)d_in[6];
    const float* wo   = (const float*)d_in[7];
    const float* bo   = (const float*)d_in[8];
    const float* tpar = (const float*)d_in[9];
    float* out = (float*)d_out;

    float *qp, *kp, *vp, *op, *xp, *wtp;
    cudaGetSymbolAddress((void**)&qp, g_q);
    cudaGetSymbolAddress((void**)&kp, g_k);
    cudaGetSymbolAddress((void**)&vp, g_v);
    cudaGetSymbolAddress((void**)&op, g_o);
    cudaGetSymbolAddress((void**)&xp, g_x);
    cudaGetSymbolAddress((void**)&wtp, g_wt);

    // prepasses: round X to tf32; transpose+round all weights (qkv packed)
    xconv<<<(MROWS * FEAT) / (4 * 256), 256>>>(x, xp);
    dim3 wg(FEAT / 32, FEAT / 32), wb(32, 8);
    wtrans<<<wg, wb>>>(wq, wtp + 0 * (size_t)FEAT * FEAT);
    wtrans<<<wg, wb>>>(wk, wtp + 1 * (size_t)FEAT * FEAT);
    wtrans<<<wg, wb>>>(wv, wtp + 2 * (size_t)FEAT * FEAT);
    wtrans<<<wg, wb>>>(wo, wtp + 3 * (size_t)FEAT * FEAT);

    cudaFuncSetAttribute(tgemm_qkv, cudaFuncAttributeMaxDynamicSharedMemorySize, TG_SMEM);
    cudaFuncSetAttribute(tgemm_out, cudaFuncAttributeMaxDynamicSharedMemorySize, TG_SMEM);

    // fused QKV GEMM: N = 2304
    tgemm_qkv<<<dim3((MROWS + 127) / 128, 3 * FEAT / 128), 256, TG_SMEM>>>(
        xp, wtp, bq, bk, bv, qp, kp, vp);

    cudaFuncSetAttribute(attn_tf32, cudaFuncAttributeMaxDynamicSharedMemorySize,
                         ATT_SMEM);
    attn_tf32<<<dim3(8, HEADS, BATCH), 256, ATT_SMEM>>>(tpar, op);
    cls_row<<<dim3(BATCH, HEADS), 256>>>(op);

    tgemm_out<<<dim3((MROWS + 127) / 128, FEAT / 128), 256, TG_SMEM>>>(
        op, wtp + 3 * (size_t)FEAT * FEAT, bo, out);
}